// round 6
// baseline (speedup 1.0000x reference)
#include <cuda_runtime.h>
#include <math.h>

#define N_TOK 2048
#define D_DIM 1024
#define H_DIM 4096
#define E_NUM 8
#define R_DIM 16
#define LSCALE 2.0f
#define NSLOT (2*N_TOK)

// ---------------- scratch ----------------
__device__ float g_common[N_TOK * H_DIM];
__device__ float g_act[NSLOT * H_DIM];
__device__ float g_base2[NSLOT * D_DIM];
__device__ float g_t1[NSLOT * R_DIM];
__device__ float g_t2[NSLOT * R_DIM];
__device__ int   g_sel[NSLOT];
__device__ float g_wt[NSLOT];
__device__ int g_cnt[E_NUM];
__device__ int g_off[E_NUM];
__device__ int g_pos[E_NUM];
__device__ int g_list[NSLOT];

// ---------------- router (block 0 also zeroes expert counts) ----------------
__global__ void router_kernel(const float* __restrict__ x, const float* __restrict__ gate) {
    int t = blockIdx.x;
    if (t == 0 && threadIdx.x < E_NUM) g_cnt[threadIdx.x] = 0;
    int warp = threadIdx.x >> 5, lane = threadIdx.x & 31;
    __shared__ float logits[E_NUM];
    const float4* xr = (const float4*)(x + (size_t)t * D_DIM);
    const float4* gr = (const float4*)(gate + (size_t)warp * D_DIM);
    float s = 0.f;
    for (int i = lane; i < D_DIM / 4; i += 32) {
        float4 a = xr[i], b = gr[i];
        s += a.x * b.x + a.y * b.y + a.z * b.z + a.w * b.w;
    }
    #pragma unroll
    for (int o = 16; o; o >>= 1) s += __shfl_xor_sync(0xffffffffu, s, o);
    if (lane == 0) logits[warp] = s;
    __syncthreads();
    if (threadIdx.x == 0) {
        float best = -1e30f; int i0 = 0;
        #pragma unroll
        for (int e = 0; e < E_NUM; e++) if (logits[e] > best) { best = logits[e]; i0 = e; }
        float best2 = -1e30f; int i1 = 0;
        #pragma unroll
        for (int e = 0; e < E_NUM; e++) if (e != i0 && logits[e] > best2) { best2 = logits[e]; i1 = e; }
        float p1 = expf(best2 - best);
        float inv = 1.f / (1.f + p1);
        g_sel[t * 2 + 0] = i0; g_sel[t * 2 + 1] = i1;
        g_wt[t * 2 + 0] = inv; g_wt[t * 2 + 1] = p1 * inv;
    }
}

// ---------------- dispatch ----------------
__global__ void dispatch_count() {
    int i = blockIdx.x * 256 + threadIdx.x;
    if (i < NSLOT) atomicAdd(&g_cnt[g_sel[i]], 1);
}
__global__ void dispatch_prefix() {
    if (threadIdx.x == 0) {
        int o = 0;
        for (int e = 0; e < E_NUM; e++) { g_off[e] = o; g_pos[e] = o; o += g_cnt[e]; }
    }
}
__global__ void dispatch_scatter() {
    int i = blockIdx.x * 256 + threadIdx.x;
    if (i < NSLOT) {
        int e = g_sel[i];
        int pos = atomicAdd(&g_pos[e], 1);
        g_list[pos] = i;
    }
}

// ---------------- tf32 GEMM: C[M,N] = A[M,K] @ B[N,K]^T ----------------
// 128x128 tile, BK=32, 256 thr (8 warps 4x2), warp tile 32x64 m16n8k8.
// tf32 conversion at smem store; pair layout (k,k+4) adjacent -> LDS.64 fragments.
// Static 40KB smem + launch_bounds(256,2) -> 2 CTAs/SM.
__device__ __forceinline__ float f2tf32f(float x) {
    unsigned r;
    asm("cvt.rna.tf32.f32 %0, %1;" : "=r"(r) : "f"(x));
    return __uint_as_float(r);
}
__device__ __forceinline__ void mma_tf32(float* c, const unsigned* a, const unsigned* b) {
    asm volatile(
        "mma.sync.aligned.m16n8k8.row.col.f32.tf32.tf32.f32 "
        "{%0,%1,%2,%3}, {%4,%5,%6,%7}, {%8,%9}, {%0,%1,%2,%3};"
        : "+f"(c[0]), "+f"(c[1]), "+f"(c[2]), "+f"(c[3])
        : "r"(a[0]), "r"(a[1]), "r"(a[2]), "r"(a[3]), "r"(b[0]), "r"(b[1]));
}

#define GSTR 40   // 32 + 8 pad: conflict-free LDS.64 (banks 8g+2tg distinct per phase)

__global__ __launch_bounds__(256, 2)
void gemm_tf32_kernel(const float* __restrict__ A, const float* __restrict__ B,
                      float* __restrict__ C, int M, int N, int K) {
    const int BM = 128, BN = 128, BK = 32;
    __shared__ float As[BM * GSTR];   // 20KB
    __shared__ float Bs[BN * GSTR];   // 20KB
    int bm = blockIdx.y * BM, bn = blockIdx.x * BN;
    int tid = threadIdx.x;
    int lane = tid & 31, wid = tid >> 5;
    int wm = (wid >> 1) * 32, wn = (wid & 1) * 64;
    int g = lane >> 2, tg = lane & 3;

    // each thread owns row = tid>>1, q0 = (tid&1)*4 (k-range q0*4 .. q0*4+15)
    int ldrow = tid >> 1;
    int q0 = (tid & 1) * 4;
    int mm0 = q0 >> 1;          // 0 or 2
    const float* Arow = A + (size_t)(bm + ldrow) * K + q0 * 4;
    const float* Brow = B + (size_t)(bn + ldrow) * K + q0 * 4;
    float* Asw = &As[ldrow * GSTR + mm0 * 8];
    float* Bsw = &Bs[ldrow * GSTR + mm0 * 8];

    float acc[2][8][4];
    #pragma unroll
    for (int mt = 0; mt < 2; mt++)
        #pragma unroll
        for (int nt = 0; nt < 8; nt++)
            #pragma unroll
            for (int i = 0; i < 4; i++) acc[mt][nt][i] = 0.f;

    float4 ra[4], rb[4];

    // prologue: load + store tile 0
    #pragma unroll
    for (int l = 0; l < 4; l++) {
        ra[l] = *(const float4*)(Arow + l * 4);
        rb[l] = *(const float4*)(Brow + l * 4);
    }
    #pragma unroll
    for (int pr = 0; pr < 2; pr++) {
        const float* a0 = (const float*)&ra[2 * pr];
        const float* a1 = (const float*)&ra[2 * pr + 1];
        const float* b0 = (const float*)&rb[2 * pr];
        const float* b1 = (const float*)&rb[2 * pr + 1];
        #pragma unroll
        for (int j = 0; j < 4; j++) {
            *(float2*)&Asw[pr * 8 + 2 * j] = make_float2(f2tf32f(a0[j]), f2tf32f(a1[j]));
            *(float2*)&Bsw[pr * 8 + 2 * j] = make_float2(f2tf32f(b0[j]), f2tf32f(b1[j]));
        }
    }
    __syncthreads();

    for (int k0 = 0; k0 < K; k0 += BK) {
        bool more = (k0 + BK) < K;
        if (more) {
            #pragma unroll
            for (int l = 0; l < 4; l++) {
                ra[l] = *(const float4*)(Arow + k0 + BK + l * 4);
                rb[l] = *(const float4*)(Brow + k0 + BK + l * 4);
            }
        }
        #pragma unroll
        for (int kg = 0; kg < 4; kg++) {
            uint2 av[2][2], bv[8];
            #pragma unroll
            for (int mt = 0; mt < 2; mt++) {
                av[mt][0] = *(const uint2*)&As[(wm + mt * 16 + g) * GSTR + kg * 8 + tg * 2];
                av[mt][1] = *(const uint2*)&As[(wm + mt * 16 + g + 8) * GSTR + kg * 8 + tg * 2];
            }
            #pragma unroll
            for (int nt = 0; nt < 8; nt++)
                bv[nt] = *(const uint2*)&Bs[(wn + nt * 8 + g) * GSTR + kg * 8 + tg * 2];
            #pragma unroll
            for (int mt = 0; mt < 2; mt++) {
                unsigned af[4] = { av[mt][0].x, av[mt][1].x, av[mt][0].y, av[mt][1].y };
                #pragma unroll
                for (int nt = 0; nt < 8; nt++) {
                    unsigned bf[2] = { bv[nt].x, bv[nt].y };
                    mma_tf32(acc[mt][nt], af, bf);
                }
            }
        }
        __syncthreads();
        if (more) {
            #pragma unroll
            for (int pr = 0; pr < 2; pr++) {
                const float* a0 = (const float*)&ra[2 * pr];
                const float* a1 = (const float*)&ra[2 * pr + 1];
                const float* b0 = (const float*)&rb[2 * pr];
                const float* b1 = (const float*)&rb[2 * pr + 1];
                #pragma unroll
                for (int j = 0; j < 4; j++) {
                    *(float2*)&Asw[pr * 8 + 2 * j] = make_float2(f2tf32f(a0[j]), f2tf32f(a1[j]));
                    *(float2*)&Bsw[pr * 8 + 2 * j] = make_float2(f2tf32f(b0[j]), f2tf32f(b1[j]));
                }
            }
            __syncthreads();
        }
    }

    #pragma unroll
    for (int mt = 0; mt < 2; mt++) {
        #pragma unroll
        for (int nt = 0; nt < 8; nt++) {
            int r0 = bm + wm + mt * 16 + g;
            int c0 = bn + wn + nt * 8 + 2 * tg;
            C[(size_t)r0 * N + c0]           = acc[mt][nt][0];
            C[(size_t)r0 * N + c0 + 1]       = acc[mt][nt][1];
            C[(size_t)(r0 + 8) * N + c0]     = acc[mt][nt][2];
            C[(size_t)(r0 + 8) * N + c0 + 1] = acc[mt][nt][3];
        }
    }
}

// ---------------- grouped rank-16 down-projection: 8 slots/block, 1 slot/warp ----------------
#define GL_G 8
#define GL_KC 128
__global__ __launch_bounds__(256)
void lora_in_grouped(const float* __restrict__ X, const float* __restrict__ Amat,
                     float* __restrict__ Tout, int K, int tok_row) {
    int e = blockIdx.y;
    int n_e = g_cnt[e];
    int base = blockIdx.x * GL_G;
    if (base >= n_e) return;
    __shared__ float As[R_DIM][GL_KC];
    __shared__ int sl[GL_G];
    int tid = threadIdx.x, lane = tid & 31, w = tid >> 5;
    if (tid < GL_G) {
        int j = base + tid;
        sl[tid] = (j < n_e) ? g_list[g_off[e] + j] : -1;
    }
    __syncthreads();
    int p = sl[w];
    int row = (p < 0) ? 0 : (tok_row ? (p >> 1) : p);
    const float* xr = X + (size_t)row * K;

    float acc[R_DIM];
    #pragma unroll
    for (int r = 0; r < R_DIM; r++) acc[r] = 0.f;

    const float* Ae = Amat + (size_t)e * R_DIM * K;
    for (int k0 = 0; k0 < K; k0 += GL_KC) {
        __syncthreads();
        #pragma unroll
        for (int l = 0; l < 2; l++) {
            int i = tid * 2 + l;
            int r = i >> 5, kq = i & 31;
            *(float4*)&As[r][kq * 4] = *(const float4*)(Ae + (size_t)r * K + k0 + kq * 4);
        }
        __syncthreads();
        float4 xv = *(const float4*)(xr + k0 + lane * 4);
        #pragma unroll
        for (int r = 0; r < R_DIM; r++) {
            float4 a4 = *(const float4*)&As[r][lane * 4];
            acc[r] += xv.x * a4.x + xv.y * a4.y + xv.z * a4.z + xv.w * a4.w;
        }
    }
    #pragma unroll
    for (int r = 0; r < R_DIM; r++) {
        float v = acc[r];
        v += __shfl_xor_sync(0xffffffffu, v, 16);
        v += __shfl_xor_sync(0xffffffffu, v, 8);
        v += __shfl_xor_sync(0xffffffffu, v, 4);
        v += __shfl_xor_sync(0xffffffffu, v, 2);
        v += __shfl_xor_sync(0xffffffffu, v, 1);
        if (lane == 0 && p >= 0) Tout[p * R_DIM + r] = v;
    }
}

// ---------------- grouped fc1 epilogue: 16 slots x 1024-h chunk per block ----------------
#define GA_G 16
#define HSPLIT 4
#define HCH (H_DIM / HSPLIT)
__device__ __forceinline__ float fast_silu(float v) {
    float t, sig;
    asm("ex2.approx.f32 %0, %1;" : "=f"(t) : "f"(-v * 1.4426950408889634f));
    asm("rcp.approx.f32 %0, %1;" : "=f"(sig) : "f"(1.f + t));
    return v * sig;
}
__global__ __launch_bounds__(256)
void act_grouped(const float* __restrict__ B1mat, const float* __restrict__ b1) {
    int e = blockIdx.z;
    int n_e = g_cnt[e];
    int base = blockIdx.x * GA_G;
    if (base >= n_e) return;
    int cnt = min(GA_G, n_e - base);
    int h0 = blockIdx.y * HCH;
    __shared__ float t1s[GA_G][R_DIM];
    __shared__ int sl[GA_G];
    int tid = threadIdx.x;
    if (tid < GA_G) sl[tid] = (tid < cnt) ? g_list[g_off[e] + base + tid] : -1;
    __syncthreads();
    if (tid < GA_G * R_DIM) {
        int s = tid >> 4, r = tid & 15;
        int ps = sl[s];
        t1s[s][r] = (ps >= 0) ? g_t1[ps * R_DIM + r] : 0.f;
    }
    __syncthreads();
    const float* B1e = B1mat + (size_t)e * H_DIM * R_DIM;
    for (int h = h0 + tid; h < h0 + HCH; h += 256) {
        const float4* br = (const float4*)(B1e + (size_t)h * R_DIM);
        float4 v0 = br[0], v1 = br[1], v2 = br[2], v3 = br[3];
        float bb = b1[h];
        #pragma unroll
        for (int s = 0; s < GA_G; s++) {
            int ps = sl[s];
            if (ps >= 0) {
                float lor = v0.x * t1s[s][0]  + v0.y * t1s[s][1]  + v0.z * t1s[s][2]  + v0.w * t1s[s][3]
                          + v1.x * t1s[s][4]  + v1.y * t1s[s][5]  + v1.z * t1s[s][6]  + v1.w * t1s[s][7]
                          + v2.x * t1s[s][8]  + v2.y * t1s[s][9]  + v2.z * t1s[s][10] + v2.w * t1s[s][11]
                          + v3.x * t1s[s][12] + v3.y * t1s[s][13] + v3.z * t1s[s][14] + v3.w * t1s[s][15];
                float val = g_common[(size_t)(ps >> 1) * H_DIM + h] + bb + LSCALE * lor;
                g_act[(size_t)ps * H_DIM + h] = fast_silu(val);
            }
        }
    }
}

// ---------------- combine ----------------
__global__ void combine_kernel(const float* __restrict__ B2mat, const float* __restrict__ b2,
                               float* __restrict__ out) {
    int t = blockIdx.x;
    __shared__ float t2s[2][R_DIM];
    __shared__ float wsh[2];
    __shared__ int esh[2];
    if (threadIdx.x < 2 * R_DIM) t2s[threadIdx.x >> 4][threadIdx.x & 15] = g_t2[t * 2 * R_DIM + threadIdx.x];
    if (threadIdx.x < 2) { wsh[threadIdx.x] = g_wt[t * 2 + threadIdx.x]; esh[threadIdx.x] = g_sel[t * 2 + threadIdx.x]; }
    __syncthreads();
    for (int d = threadIdx.x; d < D_DIM; d += blockDim.x) {
        float val = 0.f;
        #pragma unroll
        for (int k = 0; k < 2; k++) {
            const float4* br = (const float4*)(B2mat + ((size_t)esh[k] * D_DIM + d) * R_DIM);
            float lor = 0.f;
            #pragma unroll
            for (int q = 0; q < 4; q++) {
                float4 v = br[q];
                lor += v.x * t2s[k][q * 4 + 0] + v.y * t2s[k][q * 4 + 1]
                     + v.z * t2s[k][q * 4 + 2] + v.w * t2s[k][q * 4 + 3];
            }
            val += wsh[k] * (g_base2[((size_t)t * 2 + k) * D_DIM + d] + b2[d] + LSCALE * lor);
        }
        out[(size_t)t * D_DIM + d] = val;
    }
}

// ---------------- launch ----------------
extern "C" void kernel_launch(void* const* d_in, const int* in_sizes, int n_in,
                              void* d_out, int out_size) {
    const float* x    = (const float*)d_in[0];
    const float* gate = (const float*)d_in[1];
    const float* W1   = (const float*)d_in[2];
    const float* b1   = (const float*)d_in[3];
    const float* W2   = (const float*)d_in[4];
    const float* b2   = (const float*)d_in[5];
    const float* A1   = (const float*)d_in[6];
    const float* B1   = (const float*)d_in[7];
    const float* A2   = (const float*)d_in[8];
    const float* B2   = (const float*)d_in[9];
    float* out = (float*)d_out;

    float *p_common, *p_act, *p_base2, *p_t1, *p_t2;
    cudaGetSymbolAddress((void**)&p_common, g_common);
    cudaGetSymbolAddress((void**)&p_act,    g_act);
    cudaGetSymbolAddress((void**)&p_base2,  g_base2);
    cudaGetSymbolAddress((void**)&p_t1,     g_t1);
    cudaGetSymbolAddress((void**)&p_t2,     g_t2);

    // 1. router (+ zero counts)
    router_kernel<<<N_TOK, 256>>>(x, gate);

    // 2. dispatch
    dispatch_count<<<NSLOT / 256, 256>>>();
    dispatch_prefix<<<1, 32>>>();
    dispatch_scatter<<<NSLOT / 256, 256>>>();

    // 3. common_fc1 = X @ W1^T
    {
        dim3 grid(H_DIM / 128, N_TOK / 128);
        gemm_tf32_kernel<<<grid, 256>>>(x, W1, p_common, N_TOK, H_DIM, D_DIM);
    }

    // 4. t1 = x @ A1[e]^T
    lora_in_grouped<<<dim3(NSLOT / GL_G, E_NUM), 256>>>(x, A1, p_t1, D_DIM, 1);

    // 5. a = silu(common + b1 + scale * t1 @ B1[e]^T)
    act_grouped<<<dim3(NSLOT / GA_G, HSPLIT, E_NUM), 256>>>(B1, b1);

    // 6. base2 = a @ W2^T
    {
        dim3 grid(D_DIM / 128, NSLOT / 128);
        gemm_tf32_kernel<<<grid, 256>>>(p_act, W2, p_base2, NSLOT, D_DIM, H_DIM);
    }

    // 7. t2 = a @ A2[e]^T
    lora_in_grouped<<<dim3(NSLOT / GL_G, E_NUM), 256>>>(p_act, A2, p_t2, H_DIM, 0);

    // 8. out
    combine_kernel<<<N_TOK, 256>>>(B2, b2, out);
}

// round 8
// speedup vs baseline: 2.0264x; 2.0264x over previous
#include <cuda_runtime.h>
#include <cuda_fp16.h>
#include <math.h>
#include <stdint.h>

#define N_TOK 2048
#define D_DIM 1024
#define H_DIM 4096
#define E_NUM 8
#define R_DIM 16
#define LSCALE 2.0f
#define NSLOT (2*N_TOK)

// ---------------- scratch ----------------
__device__ float g_common[N_TOK * H_DIM];
__device__ float g_act[NSLOT * H_DIM];
__device__ float g_base2[NSLOT * D_DIM];
__device__ float g_t1[NSLOT * R_DIM];
__device__ float g_t2[NSLOT * R_DIM];
__device__ int   g_sel[NSLOT];
__device__ float g_wt[NSLOT];
__device__ int g_cnt[E_NUM];
__device__ int g_off[E_NUM];
__device__ int g_pos[E_NUM];
__device__ int g_list[NSLOT];

// ---------------- router (block 0 zeroes expert counts) ----------------
__global__ void router_kernel(const float* __restrict__ x, const float* __restrict__ gate) {
    int t = blockIdx.x;
    if (t == 0 && threadIdx.x < E_NUM) g_cnt[threadIdx.x] = 0;
    int warp = threadIdx.x >> 5, lane = threadIdx.x & 31;
    __shared__ float logits[E_NUM];
    const float4* xr = (const float4*)(x + (size_t)t * D_DIM);
    const float4* gr = (const float4*)(gate + (size_t)warp * D_DIM);
    float s = 0.f;
    for (int i = lane; i < D_DIM / 4; i += 32) {
        float4 a = xr[i], b = gr[i];
        s += a.x * b.x + a.y * b.y + a.z * b.z + a.w * b.w;
    }
    #pragma unroll
    for (int o = 16; o; o >>= 1) s += __shfl_xor_sync(0xffffffffu, s, o);
    if (lane == 0) logits[warp] = s;
    __syncthreads();
    if (threadIdx.x == 0) {
        float best = -1e30f; int i0 = 0;
        #pragma unroll
        for (int e = 0; e < E_NUM; e++) if (logits[e] > best) { best = logits[e]; i0 = e; }
        float best2 = -1e30f; int i1 = 0;
        #pragma unroll
        for (int e = 0; e < E_NUM; e++) if (e != i0 && logits[e] > best2) { best2 = logits[e]; i1 = e; }
        float p1 = expf(best2 - best);
        float inv = 1.f / (1.f + p1);
        g_sel[t * 2 + 0] = i0; g_sel[t * 2 + 1] = i1;
        g_wt[t * 2 + 0] = inv; g_wt[t * 2 + 1] = p1 * inv;
    }
}

// ---------------- dispatch ----------------
__global__ void dispatch_count() {
    int i = blockIdx.x * 256 + threadIdx.x;
    if (i < NSLOT) atomicAdd(&g_cnt[g_sel[i]], 1);
}
__global__ void dispatch_prefix() {
    if (threadIdx.x == 0) {
        int o = 0;
        for (int e = 0; e < E_NUM; e++) { g_off[e] = o; g_pos[e] = o; o += g_cnt[e]; }
    }
}
__global__ void dispatch_scatter() {
    int i = blockIdx.x * 256 + threadIdx.x;
    if (i < NSLOT) {
        int e = g_sel[i];
        int pos = atomicAdd(&g_pos[e], 1);
        g_list[pos] = i;
    }
}

// ---------------- fp16 tensor-core GEMM:  C[M,N] = A[M,K] @ B[N,K]^T ----------------
// 128x128 tile, BK=32, 256 threads (8 warps 4x2), warp tile 32x64 via m16n8k16.
// fp16 conversion at smem store; packed LDS.32 fragment loads, stride-40 halves
// (bank = 20g + k/2 + tg mod 32: all 32 lanes distinct -> conflict-free).
__device__ __forceinline__ void mma_f16(float* c, const unsigned* a, const unsigned* b) {
    asm volatile(
        "mma.sync.aligned.m16n8k16.row.col.f32.f16.f16.f32 "
        "{%0,%1,%2,%3}, {%4,%5,%6,%7}, {%8,%9}, {%0,%1,%2,%3};"
        : "+f"(c[0]), "+f"(c[1]), "+f"(c[2]), "+f"(c[3])
        : "r"(a[0]), "r"(a[1]), "r"(a[2]), "r"(a[3]), "r"(b[0]), "r"(b[1]));
}

#define GSTRH 40   // halves per row (32 + 8 pad)

__global__ __launch_bounds__(256)
void gemm_f16_kernel(const float* __restrict__ A, const float* __restrict__ B,
                     float* __restrict__ C, int M, int N, int K) {
    const int BM = 128, BN = 128, BK = 32;
    __shared__ __half As[BM * GSTRH];   // 10KB
    __shared__ __half Bs[BN * GSTRH];   // 10KB
    int bm = blockIdx.y * BM, bn = blockIdx.x * BN;
    int tid = threadIdx.x;
    int lane = tid & 31, wid = tid >> 5;
    int wm = (wid >> 1) * 32, wn = (wid & 1) * 64;
    int g = lane >> 2, tg = lane & 3;

    float acc[2][8][4];
    #pragma unroll
    for (int mt = 0; mt < 2; mt++)
        #pragma unroll
        for (int nt = 0; nt < 8; nt++)
            #pragma unroll
            for (int i = 0; i < 4; i++) acc[mt][nt][i] = 0.f;

    float4 ra[4], rb[4];

    // prologue: load K-tile 0
    #pragma unroll
    for (int l = 0; l < 4; l++) {
        int idx = tid * 4 + l;
        int row = idx >> 3, q = idx & 7;
        ra[l] = *(const float4*)(A + (size_t)(bm + row) * K + q * 4);
        rb[l] = *(const float4*)(B + (size_t)(bn + row) * K + q * 4);
    }
    #pragma unroll
    for (int l = 0; l < 4; l++) {
        int idx = tid * 4 + l;
        int row = idx >> 3, q = idx & 7;
        __half2 a01 = __floats2half2_rn(ra[l].x, ra[l].y);
        __half2 a23 = __floats2half2_rn(ra[l].z, ra[l].w);
        __half2 b01 = __floats2half2_rn(rb[l].x, rb[l].y);
        __half2 b23 = __floats2half2_rn(rb[l].z, rb[l].w);
        *(__half2*)&As[row * GSTRH + q * 4]     = a01;
        *(__half2*)&As[row * GSTRH + q * 4 + 2] = a23;
        *(__half2*)&Bs[row * GSTRH + q * 4]     = b01;
        *(__half2*)&Bs[row * GSTRH + q * 4 + 2] = b23;
    }
    __syncthreads();

    for (int k0 = 0; k0 < K; k0 += BK) {
        bool more = (k0 + BK) < K;
        if (more) {
            #pragma unroll
            for (int l = 0; l < 4; l++) {
                int idx = tid * 4 + l;
                int row = idx >> 3, q = idx & 7;
                ra[l] = *(const float4*)(A + (size_t)(bm + row) * K + k0 + BK + q * 4);
                rb[l] = *(const float4*)(B + (size_t)(bn + row) * K + k0 + BK + q * 4);
            }
        }
        // compute: 2 K-16 steps
        #pragma unroll
        for (int kg = 0; kg < 2; kg++) {
            int kb = kg * 16 + 2 * tg;
            unsigned av[2][4], bv[8][2];
            #pragma unroll
            for (int mt = 0; mt < 2; mt++) {
                int r0 = wm + mt * 16 + g;
                av[mt][0] = *(const unsigned*)&As[r0 * GSTRH + kb];
                av[mt][1] = *(const unsigned*)&As[(r0 + 8) * GSTRH + kb];
                av[mt][2] = *(const unsigned*)&As[r0 * GSTRH + kb + 8];
                av[mt][3] = *(const unsigned*)&As[(r0 + 8) * GSTRH + kb + 8];
            }
            #pragma unroll
            for (int nt = 0; nt < 8; nt++) {
                int c0 = wn + nt * 8 + g;
                bv[nt][0] = *(const unsigned*)&Bs[c0 * GSTRH + kb];
                bv[nt][1] = *(const unsigned*)&Bs[c0 * GSTRH + kb + 8];
            }
            #pragma unroll
            for (int mt = 0; mt < 2; mt++)
                #pragma unroll
                for (int nt = 0; nt < 8; nt++)
                    mma_f16(acc[mt][nt], av[mt], bv[nt]);
        }
        __syncthreads();
        if (more) {
            #pragma unroll
            for (int l = 0; l < 4; l++) {
                int idx = tid * 4 + l;
                int row = idx >> 3, q = idx & 7;
                __half2 a01 = __floats2half2_rn(ra[l].x, ra[l].y);
                __half2 a23 = __floats2half2_rn(ra[l].z, ra[l].w);
                __half2 b01 = __floats2half2_rn(rb[l].x, rb[l].y);
                __half2 b23 = __floats2half2_rn(rb[l].z, rb[l].w);
                *(__half2*)&As[row * GSTRH + q * 4]     = a01;
                *(__half2*)&As[row * GSTRH + q * 4 + 2] = a23;
                *(__half2*)&Bs[row * GSTRH + q * 4]     = b01;
                *(__half2*)&Bs[row * GSTRH + q * 4 + 2] = b23;
            }
            __syncthreads();
        }
    }

    // epilogue (same C mapping as m16n8k8)
    #pragma unroll
    for (int mt = 0; mt < 2; mt++) {
        #pragma unroll
        for (int nt = 0; nt < 8; nt++) {
            int r0 = bm + wm + mt * 16 + g;
            int c0 = bn + wn + nt * 8 + 2 * tg;
            C[(size_t)r0 * N + c0]           = acc[mt][nt][0];
            C[(size_t)r0 * N + c0 + 1]       = acc[mt][nt][1];
            C[(size_t)(r0 + 8) * N + c0]     = acc[mt][nt][2];
            C[(size_t)(r0 + 8) * N + c0 + 1] = acc[mt][nt][3];
        }
    }
}

// ---------------- grouped rank-16 down-projection (R5 version) ----------------
#define GL_G 32
#define GL_KC 128
__global__ __launch_bounds__(256)
void lora_in_grouped(const float* __restrict__ X, const float* __restrict__ Amat,
                     float* __restrict__ Tout, int K, int tok_row) {
    int e = blockIdx.y;
    int n_e = g_cnt[e];
    int base = blockIdx.x * GL_G;
    if (base >= n_e) return;
    __shared__ float As[R_DIM][GL_KC];
    __shared__ int sl[GL_G];
    int tid = threadIdx.x, lane = tid & 31, w = tid >> 5;
    if (tid < GL_G) {
        int j = base + tid;
        sl[tid] = (j < n_e) ? g_list[g_off[e] + j] : -1;
    }
    __syncthreads();
    int p[4];
    const float* xr[4];
    #pragma unroll
    for (int s = 0; s < 4; s++) {
        p[s] = sl[w * 4 + s];
        int row = (p[s] < 0) ? 0 : (tok_row ? (p[s] >> 1) : p[s]);
        xr[s] = X + (size_t)row * K;
    }
    float acc[4][R_DIM];
    #pragma unroll
    for (int s = 0; s < 4; s++)
        #pragma unroll
        for (int r = 0; r < R_DIM; r++) acc[s][r] = 0.f;

    const float* Ae = Amat + (size_t)e * R_DIM * K;
    for (int k0 = 0; k0 < K; k0 += GL_KC) {
        __syncthreads();
        #pragma unroll
        for (int l = 0; l < 2; l++) {
            int i = tid * 2 + l;
            int r = i >> 5, kq = i & 31;
            *(float4*)&As[r][kq * 4] = *(const float4*)(Ae + (size_t)r * K + k0 + kq * 4);
        }
        __syncthreads();
        float4 xv[4];
        #pragma unroll
        for (int s = 0; s < 4; s++) xv[s] = *(const float4*)(xr[s] + k0 + lane * 4);
        #pragma unroll
        for (int r = 0; r < R_DIM; r++) {
            float4 a4 = *(const float4*)&As[r][lane * 4];
            #pragma unroll
            for (int s = 0; s < 4; s++)
                acc[s][r] += xv[s].x * a4.x + xv[s].y * a4.y + xv[s].z * a4.z + xv[s].w * a4.w;
        }
    }
    #pragma unroll
    for (int s = 0; s < 4; s++) {
        #pragma unroll
        for (int r = 0; r < R_DIM; r++) {
            float v = acc[s][r];
            v += __shfl_xor_sync(0xffffffffu, v, 16);
            v += __shfl_xor_sync(0xffffffffu, v, 8);
            v += __shfl_xor_sync(0xffffffffu, v, 4);
            v += __shfl_xor_sync(0xffffffffu, v, 2);
            v += __shfl_xor_sync(0xffffffffu, v, 1);
            if (lane == 0 && p[s] >= 0) Tout[p[s] * R_DIM + r] = v;
        }
    }
}

// ---------------- grouped fc1 epilogue (R5 version) ----------------
#define GA_G 16
__global__ __launch_bounds__(256)
void act_grouped(const float* __restrict__ B1mat, const float* __restrict__ b1) {
    int e = blockIdx.y;
    int n_e = g_cnt[e];
    int base = blockIdx.x * GA_G;
    if (base >= n_e) return;
    int cnt = min(GA_G, n_e - base);
    __shared__ float t1s[GA_G][R_DIM];
    __shared__ int sl[GA_G];
    int tid = threadIdx.x;
    if (tid < GA_G) sl[tid] = (tid < cnt) ? g_list[g_off[e] + base + tid] : -1;
    __syncthreads();
    if (tid < GA_G * R_DIM) {
        int s = tid >> 4, r = tid & 15;
        int ps = sl[s];
        t1s[s][r] = (ps >= 0) ? g_t1[ps * R_DIM + r] : 0.f;
    }
    __syncthreads();
    const float* B1e = B1mat + (size_t)e * H_DIM * R_DIM;
    for (int h = tid; h < H_DIM; h += 256) {
        const float4* br = (const float4*)(B1e + (size_t)h * R_DIM);
        float4 v0 = br[0], v1 = br[1], v2 = br[2], v3 = br[3];
        float bb = b1[h];
        #pragma unroll
        for (int s = 0; s < GA_G; s++) {
            int ps = sl[s];
            if (ps >= 0) {
                float lor = v0.x * t1s[s][0]  + v0.y * t1s[s][1]  + v0.z * t1s[s][2]  + v0.w * t1s[s][3]
                          + v1.x * t1s[s][4]  + v1.y * t1s[s][5]  + v1.z * t1s[s][6]  + v1.w * t1s[s][7]
                          + v2.x * t1s[s][8]  + v2.y * t1s[s][9]  + v2.z * t1s[s][10] + v2.w * t1s[s][11]
                          + v3.x * t1s[s][12] + v3.y * t1s[s][13] + v3.z * t1s[s][14] + v3.w * t1s[s][15];
                float val = g_common[(size_t)(ps >> 1) * H_DIM + h] + bb + LSCALE * lor;
                g_act[(size_t)ps * H_DIM + h] = val / (1.f + expf(-val));
            }
        }
    }
}

// ---------------- combine ----------------
__global__ void combine_kernel(const float* __restrict__ B2mat, const float* __restrict__ b2,
                               float* __restrict__ out) {
    int t = blockIdx.x;
    __shared__ float t2s[2][R_DIM];
    __shared__ float wsh[2];
    __shared__ int esh[2];
    if (threadIdx.x < 2 * R_DIM) t2s[threadIdx.x >> 4][threadIdx.x & 15] = g_t2[t * 2 * R_DIM + threadIdx.x];
    if (threadIdx.x < 2) { wsh[threadIdx.x] = g_wt[t * 2 + threadIdx.x]; esh[threadIdx.x] = g_sel[t * 2 + threadIdx.x]; }
    __syncthreads();
    for (int d = threadIdx.x; d < D_DIM; d += blockDim.x) {
        float val = 0.f;
        #pragma unroll
        for (int k = 0; k < 2; k++) {
            const float4* br = (const float4*)(B2mat + ((size_t)esh[k] * D_DIM + d) * R_DIM);
            float lor = 0.f;
            #pragma unroll
            for (int q = 0; q < 4; q++) {
                float4 v = br[q];
                lor += v.x * t2s[k][q * 4 + 0] + v.y * t2s[k][q * 4 + 1]
                     + v.z * t2s[k][q * 4 + 2] + v.w * t2s[k][q * 4 + 3];
            }
            val += wsh[k] * (g_base2[((size_t)t * 2 + k) * D_DIM + d] + b2[d] + LSCALE * lor);
        }
        out[(size_t)t * D_DIM + d] = val;
    }
}

// ---------------- launch ----------------
extern "C" void kernel_launch(void* const* d_in, const int* in_sizes, int n_in,
                              void* d_out, int out_size) {
    const float* x    = (const float*)d_in[0];
    const float* gate = (const float*)d_in[1];
    const float* W1   = (const float*)d_in[2];
    const float* b1   = (const float*)d_in[3];
    const float* W2   = (const float*)d_in[4];
    const float* b2   = (const float*)d_in[5];
    const float* A1   = (const float*)d_in[6];
    const float* B1   = (const float*)d_in[7];
    const float* A2   = (const float*)d_in[8];
    const float* B2   = (const float*)d_in[9];
    float* out = (float*)d_out;

    float *p_common, *p_act, *p_base2, *p_t1, *p_t2;
    cudaGetSymbolAddress((void**)&p_common, g_common);
    cudaGetSymbolAddress((void**)&p_act,    g_act);
    cudaGetSymbolAddress((void**)&p_base2,  g_base2);
    cudaGetSymbolAddress((void**)&p_t1,     g_t1);
    cudaGetSymbolAddress((void**)&p_t2,     g_t2);

    // 1. router (+ zero counts)
    router_kernel<<<N_TOK, 256>>>(x, gate);

    // 2. dispatch
    dispatch_count<<<NSLOT / 256, 256>>>();
    dispatch_prefix<<<1, 32>>>();
    dispatch_scatter<<<NSLOT / 256, 256>>>();

    // 3. common_fc1 = X @ W1^T
    {
        dim3 grid(H_DIM / 128, N_TOK / 128);
        gemm_f16_kernel<<<grid, 256>>>(x, W1, p_common, N_TOK, H_DIM, D_DIM);
    }

    // 4. t1 = x @ A1[e]^T
    lora_in_grouped<<<dim3(NSLOT / GL_G, E_NUM), 256>>>(x, A1, p_t1, D_DIM, 1);

    // 5. a = silu(common + b1 + scale * t1 @ B1[e]^T)
    act_grouped<<<dim3(NSLOT / GA_G, E_NUM), 256>>>(B1, b1);

    // 6. base2 = a @ W2^T
    {
        dim3 grid(D_DIM / 128, NSLOT / 128);
        gemm_f16_kernel<<<grid, 256>>>(p_act, W2, p_base2, NSLOT, D_DIM, H_DIM);
    }

    // 7. t2 = a @ A2[e]^T
    lora_in_grouped<<<dim3(NSLOT / GL_G, E_NUM), 256>>>(p_act, A2, p_t2, H_DIM, 0);

    // 8. out
    combine_kernel<<<N_TOK, 256>>>(B2, b2, out);
}

// round 9
// speedup vs baseline: 2.5136x; 1.2404x over previous
#include <cuda_runtime.h>
#include <cuda_fp16.h>
#include <math.h>
#include <stdint.h>

#define N_TOK 2048
#define D_DIM 1024
#define H_DIM 4096
#define E_NUM 8
#define R_DIM 16
#define LSCALE 2.0f
#define NSLOT (2*N_TOK)

// ---------------- scratch ----------------
__device__ float  g_common[N_TOK * H_DIM];
__device__ __half g_acth[NSLOT * H_DIM];
__device__ float  g_base2[NSLOT * D_DIM];
__device__ float  g_t1[NSLOT * R_DIM];
__device__ float  g_t2[NSLOT * R_DIM];
__device__ int    g_sel[NSLOT];
__device__ float  g_wt[NSLOT];
__device__ int g_cnt[E_NUM];
__device__ int g_off[E_NUM];
__device__ int g_pos[E_NUM];
__device__ int g_list[NSLOT];
// fp16 copies of GEMM inputs
__device__ __half g_xh[N_TOK * D_DIM];
__device__ __half g_w1h[H_DIM * D_DIM];
__device__ __half g_w2h[D_DIM * H_DIM];

// ---------------- f32 -> f16 conversion (8 elems/thread) ----------------
__global__ void cvt_f32_f16(const float* __restrict__ in, __half* __restrict__ out, int n) {
    int i = (blockIdx.x * 256 + threadIdx.x) * 8;
    if (i >= n) return;
    float4 v0 = *(const float4*)(in + i);
    float4 v1 = *(const float4*)(in + i + 4);
    __half2 h[4];
    h[0] = __floats2half2_rn(v0.x, v0.y);
    h[1] = __floats2half2_rn(v0.z, v0.w);
    h[2] = __floats2half2_rn(v1.x, v1.y);
    h[3] = __floats2half2_rn(v1.z, v1.w);
    *(uint4*)(out + i) = *(uint4*)h;
}

// ---------------- router (block 0 zeroes expert counts) ----------------
__global__ void router_kernel(const float* __restrict__ x, const float* __restrict__ gate) {
    int t = blockIdx.x;
    if (t == 0 && threadIdx.x < E_NUM) g_cnt[threadIdx.x] = 0;
    int warp = threadIdx.x >> 5, lane = threadIdx.x & 31;
    __shared__ float logits[E_NUM];
    const float4* xr = (const float4*)(x + (size_t)t * D_DIM);
    const float4* gr = (const float4*)(gate + (size_t)warp * D_DIM);
    float s = 0.f;
    for (int i = lane; i < D_DIM / 4; i += 32) {
        float4 a = xr[i], b = gr[i];
        s += a.x * b.x + a.y * b.y + a.z * b.z + a.w * b.w;
    }
    #pragma unroll
    for (int o = 16; o; o >>= 1) s += __shfl_xor_sync(0xffffffffu, s, o);
    if (lane == 0) logits[warp] = s;
    __syncthreads();
    if (threadIdx.x == 0) {
        float best = -1e30f; int i0 = 0;
        #pragma unroll
        for (int e = 0; e < E_NUM; e++) if (logits[e] > best) { best = logits[e]; i0 = e; }
        float best2 = -1e30f; int i1 = 0;
        #pragma unroll
        for (int e = 0; e < E_NUM; e++) if (e != i0 && logits[e] > best2) { best2 = logits[e]; i1 = e; }
        float p1 = expf(best2 - best);
        float inv = 1.f / (1.f + p1);
        g_sel[t * 2 + 0] = i0; g_sel[t * 2 + 1] = i1;
        g_wt[t * 2 + 0] = inv; g_wt[t * 2 + 1] = p1 * inv;
    }
}

// ---------------- dispatch ----------------
__global__ void dispatch_count() {
    int i = blockIdx.x * 256 + threadIdx.x;
    if (i < NSLOT) atomicAdd(&g_cnt[g_sel[i]], 1);
}
__global__ void dispatch_prefix() {
    if (threadIdx.x == 0) {
        int o = 0;
        for (int e = 0; e < E_NUM; e++) { g_off[e] = o; g_pos[e] = o; o += g_cnt[e]; }
    }
}
__global__ void dispatch_scatter() {
    int i = blockIdx.x * 256 + threadIdx.x;
    if (i < NSLOT) {
        int e = g_sel[i];
        int pos = atomicAdd(&g_pos[e], 1);
        g_list[pos] = i;
    }
}

// ---------------- fp16 GEMM w/ cp.async 2-stage pipeline ----------------
// C[M,N] = A[M,K] @ B[N,K]^T, fp16 inputs, f32 accum.
// 128x128 tile, BK=32, 256 thr (8 warps 4x2), warp tile 32x64 via m16n8k16.
__device__ __forceinline__ void mma_f16(float* c, const unsigned* a, const unsigned* b) {
    asm volatile(
        "mma.sync.aligned.m16n8k16.row.col.f32.f16.f16.f32 "
        "{%0,%1,%2,%3}, {%4,%5,%6,%7}, {%8,%9}, {%0,%1,%2,%3};"
        : "+f"(c[0]), "+f"(c[1]), "+f"(c[2]), "+f"(c[3])
        : "r"(a[0]), "r"(a[1]), "r"(a[2]), "r"(a[3]), "r"(b[0]), "r"(b[1]));
}
__device__ __forceinline__ uint32_t smem_u32(const void* p) {
    uint32_t a;
    asm("{ .reg .u64 t; cvta.to.shared.u64 t, %1; cvt.u32.u64 %0, t; }" : "=r"(a) : "l"(p));
    return a;
}
__device__ __forceinline__ void cp_async16(uint32_t dst, const void* src) {
    asm volatile("cp.async.ca.shared.global [%0], [%1], 16;" :: "r"(dst), "l"(src));
}
#define CP_COMMIT() asm volatile("cp.async.commit_group;" ::: "memory")
#define CP_WAIT(n)  asm volatile("cp.async.wait_group %0;" :: "n"(n) : "memory")

#define GSTRH 40   // halves per row (32 + 8 pad): conflict-free fragment LDS.32
#define GHTILE (128 * GSTRH)   // halves per matrix per stage

__global__ __launch_bounds__(256)
void gemm_f16_kernel(const __half* __restrict__ A, const __half* __restrict__ B,
                     float* __restrict__ C, int M, int N, int K) {
    __shared__ __half sm[2][2][GHTILE];   // [stage][A/B]  = 40 KB
    int bm = blockIdx.y * 128, bn = blockIdx.x * 128;
    int tid = threadIdx.x;
    int lane = tid & 31, wid = tid >> 5;
    int wm = (wid >> 1) * 32, wn = (wid & 1) * 64;
    int g = lane >> 2, tg = lane & 3;

    // copy slots: 512 16B-chunks per matrix per tile; 2 per thread
    int row0 = (tid * 2) >> 2,     q0 = (tid * 2) & 3;
    int row1 = (tid * 2 + 1) >> 2, q1 = (tid * 2 + 1) & 3;
    const __half* Ap0 = A + (size_t)(bm + row0) * K + q0 * 8;
    const __half* Ap1 = A + (size_t)(bm + row1) * K + q1 * 8;
    const __half* Bp0 = B + (size_t)(bn + row0) * K + q0 * 8;
    const __half* Bp1 = B + (size_t)(bn + row1) * K + q1 * 8;
    uint32_t dA0[2], dA1[2], dB0[2], dB1[2];
    #pragma unroll
    for (int s = 0; s < 2; s++) {
        dA0[s] = smem_u32(&sm[s][0][row0 * GSTRH + q0 * 8]);
        dA1[s] = smem_u32(&sm[s][0][row1 * GSTRH + q1 * 8]);
        dB0[s] = smem_u32(&sm[s][1][row0 * GSTRH + q0 * 8]);
        dB1[s] = smem_u32(&sm[s][1][row1 * GSTRH + q1 * 8]);
    }

    float acc[2][8][4];
    #pragma unroll
    for (int mt = 0; mt < 2; mt++)
        #pragma unroll
        for (int nt = 0; nt < 8; nt++)
            #pragma unroll
            for (int i = 0; i < 4; i++) acc[mt][nt][i] = 0.f;

    int ntk = K >> 5;
    // prologue: stage 0
    cp_async16(dA0[0], Ap0); cp_async16(dA1[0], Ap1);
    cp_async16(dB0[0], Bp0); cp_async16(dB1[0], Bp1);
    CP_COMMIT();

    for (int kt = 0; kt < ntk; kt++) {
        int b = kt & 1;
        if (kt + 1 < ntk) {
            int ko = (kt + 1) * 32;
            int s = b ^ 1;
            cp_async16(dA0[s], Ap0 + ko); cp_async16(dA1[s], Ap1 + ko);
            cp_async16(dB0[s], Bp0 + ko); cp_async16(dB1[s], Bp1 + ko);
            CP_COMMIT();
            CP_WAIT(1);
        } else {
            CP_WAIT(0);
        }
        __syncthreads();
        const __half* As = sm[b][0];
        const __half* Bs = sm[b][1];
        #pragma unroll
        for (int kg = 0; kg < 2; kg++) {
            int kb = kg * 16 + 2 * tg;
            unsigned av[2][4], bv[8][2];
            #pragma unroll
            for (int mt = 0; mt < 2; mt++) {
                int r0 = wm + mt * 16 + g;
                av[mt][0] = *(const unsigned*)&As[r0 * GSTRH + kb];
                av[mt][1] = *(const unsigned*)&As[(r0 + 8) * GSTRH + kb];
                av[mt][2] = *(const unsigned*)&As[r0 * GSTRH + kb + 8];
                av[mt][3] = *(const unsigned*)&As[(r0 + 8) * GSTRH + kb + 8];
            }
            #pragma unroll
            for (int nt = 0; nt < 8; nt++) {
                int c0 = wn + nt * 8 + g;
                bv[nt][0] = *(const unsigned*)&Bs[c0 * GSTRH + kb];
                bv[nt][1] = *(const unsigned*)&Bs[c0 * GSTRH + kb + 8];
            }
            #pragma unroll
            for (int mt = 0; mt < 2; mt++)
                #pragma unroll
                for (int nt = 0; nt < 8; nt++)
                    mma_f16(acc[mt][nt], av[mt], bv[nt]);
        }
        __syncthreads();
    }

    #pragma unroll
    for (int mt = 0; mt < 2; mt++) {
        #pragma unroll
        for (int nt = 0; nt < 8; nt++) {
            int r0 = bm + wm + mt * 16 + g;
            int c0 = bn + wn + nt * 8 + 2 * tg;
            C[(size_t)r0 * N + c0]           = acc[mt][nt][0];
            C[(size_t)r0 * N + c0 + 1]       = acc[mt][nt][1];
            C[(size_t)(r0 + 8) * N + c0]     = acc[mt][nt][2];
            C[(size_t)(r0 + 8) * N + c0 + 1] = acc[mt][nt][3];
        }
    }
}

// ---------------- grouped rank-16 down-projection (fp32 input) ----------------
#define GL_G 32
#define GL_KC 128
__global__ __launch_bounds__(256)
void lora_in_grouped(const float* __restrict__ X, const float* __restrict__ Amat,
                     float* __restrict__ Tout, int K, int tok_row) {
    int e = blockIdx.y;
    int n_e = g_cnt[e];
    int base = blockIdx.x * GL_G;
    if (base >= n_e) return;
    __shared__ float As[R_DIM][GL_KC];
    __shared__ int sl[GL_G];
    int tid = threadIdx.x, lane = tid & 31, w = tid >> 5;
    if (tid < GL_G) {
        int j = base + tid;
        sl[tid] = (j < n_e) ? g_list[g_off[e] + j] : -1;
    }
    __syncthreads();
    int p[4];
    const float* xr[4];
    #pragma unroll
    for (int s = 0; s < 4; s++) {
        p[s] = sl[w * 4 + s];
        int row = (p[s] < 0) ? 0 : (tok_row ? (p[s] >> 1) : p[s]);
        xr[s] = X + (size_t)row * K;
    }
    float acc[4][R_DIM];
    #pragma unroll
    for (int s = 0; s < 4; s++)
        #pragma unroll
        for (int r = 0; r < R_DIM; r++) acc[s][r] = 0.f;

    const float* Ae = Amat + (size_t)e * R_DIM * K;
    for (int k0 = 0; k0 < K; k0 += GL_KC) {
        __syncthreads();
        #pragma unroll
        for (int l = 0; l < 2; l++) {
            int i = tid * 2 + l;
            int r = i >> 5, kq = i & 31;
            *(float4*)&As[r][kq * 4] = *(const float4*)(Ae + (size_t)r * K + k0 + kq * 4);
        }
        __syncthreads();
        float4 xv[4];
        #pragma unroll
        for (int s = 0; s < 4; s++) xv[s] = *(const float4*)(xr[s] + k0 + lane * 4);
        #pragma unroll
        for (int r = 0; r < R_DIM; r++) {
            float4 a4 = *(const float4*)&As[r][lane * 4];
            #pragma unroll
            for (int s = 0; s < 4; s++)
                acc[s][r] += xv[s].x * a4.x + xv[s].y * a4.y + xv[s].z * a4.z + xv[s].w * a4.w;
        }
    }
    #pragma unroll
    for (int s = 0; s < 4; s++) {
        #pragma unroll
        for (int r = 0; r < R_DIM; r++) {
            float v = acc[s][r];
            v += __shfl_xor_sync(0xffffffffu, v, 16);
            v += __shfl_xor_sync(0xffffffffu, v, 8);
            v += __shfl_xor_sync(0xffffffffu, v, 4);
            v += __shfl_xor_sync(0xffffffffu, v, 2);
            v += __shfl_xor_sync(0xffffffffu, v, 1);
            if (lane == 0 && p[s] >= 0) Tout[p[s] * R_DIM + r] = v;
        }
    }
}

// ---------------- grouped rank-16 down-projection (fp16 input rows) ----------------
__global__ __launch_bounds__(256)
void lora_in_grouped_h(const __half* __restrict__ X, const float* __restrict__ Amat,
                       float* __restrict__ Tout, int K) {
    int e = blockIdx.y;
    int n_e = g_cnt[e];
    int base = blockIdx.x * GL_G;
    if (base >= n_e) return;
    __shared__ float As[R_DIM][GL_KC];
    __shared__ int sl[GL_G];
    int tid = threadIdx.x, lane = tid & 31, w = tid >> 5;
    if (tid < GL_G) {
        int j = base + tid;
        sl[tid] = (j < n_e) ? g_list[g_off[e] + j] : -1;
    }
    __syncthreads();
    int p[4];
    const __half* xr[4];
    #pragma unroll
    for (int s = 0; s < 4; s++) {
        p[s] = sl[w * 4 + s];
        int row = (p[s] < 0) ? 0 : p[s];
        xr[s] = X + (size_t)row * K;
    }
    float acc[4][R_DIM];
    #pragma unroll
    for (int s = 0; s < 4; s++)
        #pragma unroll
        for (int r = 0; r < R_DIM; r++) acc[s][r] = 0.f;

    const float* Ae = Amat + (size_t)e * R_DIM * K;
    for (int k0 = 0; k0 < K; k0 += GL_KC) {
        __syncthreads();
        #pragma unroll
        for (int l = 0; l < 2; l++) {
            int i = tid * 2 + l;
            int r = i >> 5, kq = i & 31;
            *(float4*)&As[r][kq * 4] = *(const float4*)(Ae + (size_t)r * K + k0 + kq * 4);
        }
        __syncthreads();
        float4 xv[4];
        #pragma unroll
        for (int s = 0; s < 4; s++) {
            __half2 h01 = *(const __half2*)(xr[s] + k0 + lane * 4);
            __half2 h23 = *(const __half2*)(xr[s] + k0 + lane * 4 + 2);
            float2 f01 = __half22float2(h01);
            float2 f23 = __half22float2(h23);
            xv[s] = make_float4(f01.x, f01.y, f23.x, f23.y);
        }
        #pragma unroll
        for (int r = 0; r < R_DIM; r++) {
            float4 a4 = *(const float4*)&As[r][lane * 4];
            #pragma unroll
            for (int s = 0; s < 4; s++)
                acc[s][r] += xv[s].x * a4.x + xv[s].y * a4.y + xv[s].z * a4.z + xv[s].w * a4.w;
        }
    }
    #pragma unroll
    for (int s = 0; s < 4; s++) {
        #pragma unroll
        for (int r = 0; r < R_DIM; r++) {
            float v = acc[s][r];
            v += __shfl_xor_sync(0xffffffffu, v, 16);
            v += __shfl_xor_sync(0xffffffffu, v, 8);
            v += __shfl_xor_sync(0xffffffffu, v, 4);
            v += __shfl_xor_sync(0xffffffffu, v, 2);
            v += __shfl_xor_sync(0xffffffffu, v, 1);
            if (lane == 0 && p[s] >= 0) Tout[p[s] * R_DIM + r] = v;
        }
    }
}

// ---------------- grouped fc1 epilogue (writes fp16 activations) ----------------
#define GA_G 16
__global__ __launch_bounds__(256)
void act_grouped(const float* __restrict__ B1mat, const float* __restrict__ b1) {
    int e = blockIdx.y;
    int n_e = g_cnt[e];
    int base = blockIdx.x * GA_G;
    if (base >= n_e) return;
    int cnt = min(GA_G, n_e - base);
    __shared__ float t1s[GA_G][R_DIM];
    __shared__ int sl[GA_G];
    int tid = threadIdx.x;
    if (tid < GA_G) sl[tid] = (tid < cnt) ? g_list[g_off[e] + base + tid] : -1;
    __syncthreads();
    if (tid < GA_G * R_DIM) {
        int s = tid >> 4, r = tid & 15;
        int ps = sl[s];
        t1s[s][r] = (ps >= 0) ? g_t1[ps * R_DIM + r] : 0.f;
    }
    __syncthreads();
    const float* B1e = B1mat + (size_t)e * H_DIM * R_DIM;
    for (int h = tid; h < H_DIM; h += 256) {
        const float4* br = (const float4*)(B1e + (size_t)h * R_DIM);
        float4 v0 = br[0], v1 = br[1], v2 = br[2], v3 = br[3];
        float bb = b1[h];
        #pragma unroll
        for (int s = 0; s < GA_G; s++) {
            int ps = sl[s];
            if (ps >= 0) {
                float lor = v0.x * t1s[s][0]  + v0.y * t1s[s][1]  + v0.z * t1s[s][2]  + v0.w * t1s[s][3]
                          + v1.x * t1s[s][4]  + v1.y * t1s[s][5]  + v1.z * t1s[s][6]  + v1.w * t1s[s][7]
                          + v2.x * t1s[s][8]  + v2.y * t1s[s][9]  + v2.z * t1s[s][10] + v2.w * t1s[s][11]
                          + v3.x * t1s[s][12] + v3.y * t1s[s][13] + v3.z * t1s[s][14] + v3.w * t1s[s][15];
                float val = g_common[(size_t)(ps >> 1) * H_DIM + h] + bb + LSCALE * lor;
                g_acth[(size_t)ps * H_DIM + h] = __float2half_rn(val / (1.f + expf(-val)));
            }
        }
    }
}

// ---------------- combine ----------------
__global__ void combine_kernel(const float* __restrict__ B2mat, const float* __restrict__ b2,
                               float* __restrict__ out) {
    int t = blockIdx.x;
    __shared__ float t2s[2][R_DIM];
    __shared__ float wsh[2];
    __shared__ int esh[2];
    if (threadIdx.x < 2 * R_DIM) t2s[threadIdx.x >> 4][threadIdx.x & 15] = g_t2[t * 2 * R_DIM + threadIdx.x];
    if (threadIdx.x < 2) { wsh[threadIdx.x] = g_wt[t * 2 + threadIdx.x]; esh[threadIdx.x] = g_sel[t * 2 + threadIdx.x]; }
    __syncthreads();
    for (int d = threadIdx.x; d < D_DIM; d += blockDim.x) {
        float val = 0.f;
        #pragma unroll
        for (int k = 0; k < 2; k++) {
            const float4* br = (const float4*)(B2mat + ((size_t)esh[k] * D_DIM + d) * R_DIM);
            float lor = 0.f;
            #pragma unroll
            for (int q = 0; q < 4; q++) {
                float4 v = br[q];
                lor += v.x * t2s[k][q * 4 + 0] + v.y * t2s[k][q * 4 + 1]
                     + v.z * t2s[k][q * 4 + 2] + v.w * t2s[k][q * 4 + 3];
            }
            val += wsh[k] * (g_base2[((size_t)t * 2 + k) * D_DIM + d] + b2[d] + LSCALE * lor);
        }
        out[(size_t)t * D_DIM + d] = val;
    }
}

// ---------------- launch ----------------
extern "C" void kernel_launch(void* const* d_in, const int* in_sizes, int n_in,
                              void* d_out, int out_size) {
    const float* x    = (const float*)d_in[0];
    const float* gate = (const float*)d_in[1];
    const float* W1   = (const float*)d_in[2];
    const float* b1   = (const float*)d_in[3];
    const float* W2   = (const float*)d_in[4];
    const float* b2   = (const float*)d_in[5];
    const float* A1   = (const float*)d_in[6];
    const float* B1   = (const float*)d_in[7];
    const float* A2   = (const float*)d_in[8];
    const float* B2   = (const float*)d_in[9];
    float* out = (float*)d_out;

    float *p_common, *p_base2, *p_t1, *p_t2;
    __half *p_xh, *p_w1h, *p_w2h, *p_acth;
    cudaGetSymbolAddress((void**)&p_common, g_common);
    cudaGetSymbolAddress((void**)&p_base2,  g_base2);
    cudaGetSymbolAddress((void**)&p_t1,     g_t1);
    cudaGetSymbolAddress((void**)&p_t2,     g_t2);
    cudaGetSymbolAddress((void**)&p_xh,     g_xh);
    cudaGetSymbolAddress((void**)&p_w1h,    g_w1h);
    cudaGetSymbolAddress((void**)&p_w2h,    g_w2h);
    cudaGetSymbolAddress((void**)&p_acth,   g_acth);

    // 0. fp16 copies of GEMM inputs
    cvt_f32_f16<<<(N_TOK * D_DIM) / 2048, 256>>>(x, p_xh, N_TOK * D_DIM);
    cvt_f32_f16<<<(H_DIM * D_DIM) / 2048, 256>>>(W1, p_w1h, H_DIM * D_DIM);
    cvt_f32_f16<<<(D_DIM * H_DIM) / 2048, 256>>>(W2, p_w2h, D_DIM * H_DIM);

    // 1. router (+ zero counts)
    router_kernel<<<N_TOK, 256>>>(x, gate);

    // 2. dispatch
    dispatch_count<<<NSLOT / 256, 256>>>();
    dispatch_prefix<<<1, 32>>>();
    dispatch_scatter<<<NSLOT / 256, 256>>>();

    // 3. common_fc1 = X @ W1^T
    {
        dim3 grid(H_DIM / 128, N_TOK / 128);
        gemm_f16_kernel<<<grid, 256>>>(p_xh, p_w1h, p_common, N_TOK, H_DIM, D_DIM);
    }

    // 4. t1 = x @ A1[e]^T
    lora_in_grouped<<<dim3(NSLOT / GL_G, E_NUM), 256>>>(x, A1, p_t1, D_DIM, 1);

    // 5. a = silu(common + b1 + scale * t1 @ B1[e]^T) -> fp16
    act_grouped<<<dim3(NSLOT / GA_G, E_NUM), 256>>>(B1, b1);

    // 6. base2 = a @ W2^T
    {
        dim3 grid(D_DIM / 128, NSLOT / 128);
        gemm_f16_kernel<<<grid, 256>>>(p_acth, p_w2h, p_base2, NSLOT, D_DIM, H_DIM);
    }

    // 7. t2 = a @ A2[e]^T (fp16 act rows)
    lora_in_grouped_h<<<dim3(NSLOT / GL_G, E_NUM), 256>>>(p_acth, A2, p_t2, H_DIM);

    // 8. out
    combine_kernel<<<N_TOK, 256>>>(B2, b2, out);
}

// round 10
// speedup vs baseline: 2.6286x; 1.0458x over previous
#include <cuda_runtime.h>
#include <cuda_fp16.h>
#include <math.h>
#include <stdint.h>

#define N_TOK 2048
#define D_DIM 1024
#define H_DIM 4096
#define E_NUM 8
#define R_DIM 16
#define LSCALE 2.0f
#define NSLOT (2*N_TOK)

// ---------------- scratch ----------------
__device__ __half g_commonh[N_TOK * H_DIM];
__device__ __half g_acth[NSLOT * H_DIM];
__device__ float  g_base2[NSLOT * D_DIM];
__device__ float  g_t1[NSLOT * R_DIM];
__device__ float  g_t2[NSLOT * R_DIM];
__device__ int    g_sel[NSLOT];
__device__ float  g_wt[NSLOT];
__device__ int g_cnt[E_NUM];
__device__ int g_off[E_NUM];
__device__ int g_pos[E_NUM];
__device__ int g_list[NSLOT];
__device__ __half g_xh[N_TOK * D_DIM];
__device__ __half g_w1h[H_DIM * D_DIM];
__device__ __half g_w2h[D_DIM * H_DIM];

// ---------------- f32 -> f16 conversion (block 0 also zeroes expert counts) ----------------
__global__ void cvt_f32_f16(const float* __restrict__ in, __half* __restrict__ out, int n) {
    if (blockIdx.x == 0 && threadIdx.x < E_NUM) g_cnt[threadIdx.x] = 0;
    int i = (blockIdx.x * 256 + threadIdx.x) * 8;
    if (i >= n) return;
    float4 v0 = *(const float4*)(in + i);
    float4 v1 = *(const float4*)(in + i + 4);
    __half2 h[4];
    h[0] = __floats2half2_rn(v0.x, v0.y);
    h[1] = __floats2half2_rn(v0.z, v0.w);
    h[2] = __floats2half2_rn(v1.x, v1.y);
    h[3] = __floats2half2_rn(v1.z, v1.w);
    *(uint4*)(out + i) = *(uint4*)h;
}

// ---------------- router (fused expert count) ----------------
__global__ void router_kernel(const float* __restrict__ x, const float* __restrict__ gate) {
    int t = blockIdx.x;
    int warp = threadIdx.x >> 5, lane = threadIdx.x & 31;
    __shared__ float logits[E_NUM];
    const float4* xr = (const float4*)(x + (size_t)t * D_DIM);
    const float4* gr = (const float4*)(gate + (size_t)warp * D_DIM);
    float s = 0.f;
    for (int i = lane; i < D_DIM / 4; i += 32) {
        float4 a = xr[i], b = gr[i];
        s += a.x * b.x + a.y * b.y + a.z * b.z + a.w * b.w;
    }
    #pragma unroll
    for (int o = 16; o; o >>= 1) s += __shfl_xor_sync(0xffffffffu, s, o);
    if (lane == 0) logits[warp] = s;
    __syncthreads();
    if (threadIdx.x == 0) {
        float best = -1e30f; int i0 = 0;
        #pragma unroll
        for (int e = 0; e < E_NUM; e++) if (logits[e] > best) { best = logits[e]; i0 = e; }
        float best2 = -1e30f; int i1 = 0;
        #pragma unroll
        for (int e = 0; e < E_NUM; e++) if (e != i0 && logits[e] > best2) { best2 = logits[e]; i1 = e; }
        float p1 = expf(best2 - best);
        float inv = 1.f / (1.f + p1);
        g_sel[t * 2 + 0] = i0; g_sel[t * 2 + 1] = i1;
        g_wt[t * 2 + 0] = inv; g_wt[t * 2 + 1] = p1 * inv;
        atomicAdd(&g_cnt[i0], 1);
        atomicAdd(&g_cnt[i1], 1);
    }
}

// ---------------- dispatch ----------------
__global__ void dispatch_prefix() {
    if (threadIdx.x == 0) {
        int o = 0;
        for (int e = 0; e < E_NUM; e++) { g_off[e] = o; g_pos[e] = o; o += g_cnt[e]; }
    }
}
__global__ void dispatch_scatter() {
    int i = blockIdx.x * 256 + threadIdx.x;
    if (i < NSLOT) {
        int e = g_sel[i];
        int pos = atomicAdd(&g_pos[e], 1);
        g_list[pos] = i;
    }
}

// ---------------- fp16 GEMM w/ 3-stage cp.async pipeline ----------------
// C[M,N] = A[M,K] @ B[N,K]^T, fp16 in, f32 accum, CT out (float or half).
// 128x128 tile, BK=32, 256 thr (8 warps 4x2), warp tile 32x64 via m16n8k16.
__device__ __forceinline__ void mma_f16(float* c, const unsigned* a, const unsigned* b) {
    asm volatile(
        "mma.sync.aligned.m16n8k16.row.col.f32.f16.f16.f32 "
        "{%0,%1,%2,%3}, {%4,%5,%6,%7}, {%8,%9}, {%0,%1,%2,%3};"
        : "+f"(c[0]), "+f"(c[1]), "+f"(c[2]), "+f"(c[3])
        : "r"(a[0]), "r"(a[1]), "r"(a[2]), "r"(a[3]), "r"(b[0]), "r"(b[1]));
}
__device__ __forceinline__ uint32_t smem_u32(const void* p) {
    uint32_t a;
    asm("{ .reg .u64 t; cvta.to.shared.u64 t, %1; cvt.u32.u64 %0, t; }" : "=r"(a) : "l"(p));
    return a;
}
__device__ __forceinline__ void cp_async16(uint32_t dst, const void* src) {
    asm volatile("cp.async.ca.shared.global [%0], [%1], 16;" :: "r"(dst), "l"(src));
}
#define CP_COMMIT() asm volatile("cp.async.commit_group;" ::: "memory")
#define CP_WAIT(n)  asm volatile("cp.async.wait_group %0;" :: "n"(n) : "memory")

__device__ __forceinline__ void store2(float* p, float x, float y) { p[0] = x; p[1] = y; }
__device__ __forceinline__ void store2(__half* p, float x, float y) {
    *(__half2*)p = __floats2half2_rn(x, y);
}

#define GSTRH 40                      // halves per row (32 + 8 pad): conflict-free LDS.32
#define GHTILE (128 * GSTRH)          // halves per matrix per stage
#define GSTAGEB (2 * GHTILE * 2)      // bytes per stage (A+B)
#define GSMEM (3 * GSTAGEB)           // 61440 B

template <typename CT>
__global__ __launch_bounds__(256)
void gemm_f16_kernel(const __half* __restrict__ A, const __half* __restrict__ B,
                     CT* __restrict__ C, int M, int N, int K) {
    extern __shared__ __half smh[];
    uint32_t sb = smem_u32(smh);
    int bm = blockIdx.y * 128, bn = blockIdx.x * 128;
    int tid = threadIdx.x;
    int lane = tid & 31, wid = tid >> 5;
    int wm = (wid >> 1) * 32, wn = (wid & 1) * 64;
    int g = lane >> 2, tg = lane & 3;

    // copy slots: 512 16B chunks per matrix per tile; 2 per thread each
    int row0 = (tid * 2) >> 2,     q0 = (tid * 2) & 3;
    int row1 = (tid * 2 + 1) >> 2, q1 = (tid * 2 + 1) & 3;
    const char* Ap0 = (const char*)(A + (size_t)(bm + row0) * K + q0 * 8);
    const char* Ap1 = (const char*)(A + (size_t)(bm + row1) * K + q1 * 8);
    const char* Bp0 = (const char*)(B + (size_t)(bn + row0) * K + q0 * 8);
    const char* Bp1 = (const char*)(B + (size_t)(bn + row1) * K + q1 * 8);
    uint32_t oA0 = (uint32_t)(row0 * GSTRH + q0 * 8) * 2;
    uint32_t oA1 = (uint32_t)(row1 * GSTRH + q1 * 8) * 2;
    uint32_t oB0 = (uint32_t)GHTILE * 2 + oA0;
    uint32_t oB1 = (uint32_t)GHTILE * 2 + oA1;

    float acc[2][8][4];
    #pragma unroll
    for (int mt = 0; mt < 2; mt++)
        #pragma unroll
        for (int nt = 0; nt < 8; nt++)
            #pragma unroll
            for (int i = 0; i < 4; i++) acc[mt][nt][i] = 0.f;

    int ntk = K >> 5;

    // prologue: prefetch tiles 0, 1
    #pragma unroll
    for (int s = 0; s < 2; s++) {
        uint32_t st = sb + s * GSTAGEB;
        size_t ko = (size_t)s * 64;   // 32 halves
        cp_async16(st + oA0, Ap0 + ko); cp_async16(st + oA1, Ap1 + ko);
        cp_async16(st + oB0, Bp0 + ko); cp_async16(st + oB1, Bp1 + ko);
        CP_COMMIT();
    }

    for (int kt = 0; kt < ntk; kt++) {
        int b = kt % 3;
        if (kt + 1 < ntk) { CP_WAIT(1); } else { CP_WAIT(0); }
        __syncthreads();
        // prefetch tile kt+2 into stage (kt+2)%3 (buffer of tile kt-1, now free)
        if (kt + 2 < ntk) {
            int s = (kt + 2) % 3;
            uint32_t st = sb + s * GSTAGEB;
            size_t ko = (size_t)(kt + 2) * 64;
            cp_async16(st + oA0, Ap0 + ko); cp_async16(st + oA1, Ap1 + ko);
            cp_async16(st + oB0, Bp0 + ko); cp_async16(st + oB1, Bp1 + ko);
            CP_COMMIT();
        }
        const __half* As = smh + b * (2 * GHTILE);
        const __half* Bs = As + GHTILE;
        #pragma unroll
        for (int kg = 0; kg < 2; kg++) {
            int kb = kg * 16 + 2 * tg;
            unsigned av[2][4], bv[8][2];
            #pragma unroll
            for (int mt = 0; mt < 2; mt++) {
                int r0 = wm + mt * 16 + g;
                av[mt][0] = *(const unsigned*)&As[r0 * GSTRH + kb];
                av[mt][1] = *(const unsigned*)&As[(r0 + 8) * GSTRH + kb];
                av[mt][2] = *(const unsigned*)&As[r0 * GSTRH + kb + 8];
                av[mt][3] = *(const unsigned*)&As[(r0 + 8) * GSTRH + kb + 8];
            }
            #pragma unroll
            for (int nt = 0; nt < 8; nt++) {
                int c0 = wn + nt * 8 + g;
                bv[nt][0] = *(const unsigned*)&Bs[c0 * GSTRH + kb];
                bv[nt][1] = *(const unsigned*)&Bs[c0 * GSTRH + kb + 8];
            }
            #pragma unroll
            for (int mt = 0; mt < 2; mt++)
                #pragma unroll
                for (int nt = 0; nt < 8; nt++)
                    mma_f16(acc[mt][nt], av[mt], bv[nt]);
        }
    }

    #pragma unroll
    for (int mt = 0; mt < 2; mt++) {
        #pragma unroll
        for (int nt = 0; nt < 8; nt++) {
            int r0 = bm + wm + mt * 16 + g;
            int c0 = bn + wn + nt * 8 + 2 * tg;
            store2(C + (size_t)r0 * N + c0,       acc[mt][nt][0], acc[mt][nt][1]);
            store2(C + (size_t)(r0 + 8) * N + c0, acc[mt][nt][2], acc[mt][nt][3]);
        }
    }
}

// ---------------- grouped rank-16 down-projection (fp16 input rows) ----------------
#define GL_G 32
#define GL_KC 128
__global__ __launch_bounds__(256)
void lora_in_grouped_h(const __half* __restrict__ X, const float* __restrict__ Amat,
                       float* __restrict__ Tout, int K, int tok_row) {
    int e = blockIdx.y;
    int n_e = g_cnt[e];
    int base = blockIdx.x * GL_G;
    if (base >= n_e) return;
    __shared__ float As[R_DIM][GL_KC];
    __shared__ int sl[GL_G];
    int tid = threadIdx.x, lane = tid & 31, w = tid >> 5;
    if (tid < GL_G) {
        int j = base + tid;
        sl[tid] = (j < n_e) ? g_list[g_off[e] + j] : -1;
    }
    __syncthreads();
    int p[4];
    const __half* xr[4];
    #pragma unroll
    for (int s = 0; s < 4; s++) {
        p[s] = sl[w * 4 + s];
        int row = (p[s] < 0) ? 0 : (tok_row ? (p[s] >> 1) : p[s]);
        xr[s] = X + (size_t)row * K;
    }
    float acc[4][R_DIM];
    #pragma unroll
    for (int s = 0; s < 4; s++)
        #pragma unroll
        for (int r = 0; r < R_DIM; r++) acc[s][r] = 0.f;

    const float* Ae = Amat + (size_t)e * R_DIM * K;
    for (int k0 = 0; k0 < K; k0 += GL_KC) {
        __syncthreads();
        #pragma unroll
        for (int l = 0; l < 2; l++) {
            int i = tid * 2 + l;
            int r = i >> 5, kq = i & 31;
            *(float4*)&As[r][kq * 4] = *(const float4*)(Ae + (size_t)r * K + k0 + kq * 4);
        }
        __syncthreads();
        float4 xv[4];
        #pragma unroll
        for (int s = 0; s < 4; s++) {
            __half2 h01 = *(const __half2*)(xr[s] + k0 + lane * 4);
            __half2 h23 = *(const __half2*)(xr[s] + k0 + lane * 4 + 2);
            float2 f01 = __half22float2(h01);
            float2 f23 = __half22float2(h23);
            xv[s] = make_float4(f01.x, f01.y, f23.x, f23.y);
        }
        #pragma unroll
        for (int r = 0; r < R_DIM; r++) {
            float4 a4 = *(const float4*)&As[r][lane * 4];
            #pragma unroll
            for (int s = 0; s < 4; s++)
                acc[s][r] += xv[s].x * a4.x + xv[s].y * a4.y + xv[s].z * a4.z + xv[s].w * a4.w;
        }
    }
    #pragma unroll
    for (int s = 0; s < 4; s++) {
        #pragma unroll
        for (int r = 0; r < R_DIM; r++) {
            float v = acc[s][r];
            v += __shfl_xor_sync(0xffffffffu, v, 16);
            v += __shfl_xor_sync(0xffffffffu, v, 8);
            v += __shfl_xor_sync(0xffffffffu, v, 4);
            v += __shfl_xor_sync(0xffffffffu, v, 2);
            v += __shfl_xor_sync(0xffffffffu, v, 1);
            if (lane == 0 && p[s] >= 0) Tout[p[s] * R_DIM + r] = v;
        }
    }
}

// ---------------- grouped fc1 epilogue (half common in, half act out, fast silu) ----------------
#define GA_G 16
__global__ __launch_bounds__(256)
void act_grouped(const float* __restrict__ B1mat, const float* __restrict__ b1) {
    int e = blockIdx.y;
    int n_e = g_cnt[e];
    int base = blockIdx.x * GA_G;
    if (base >= n_e) return;
    int cnt = min(GA_G, n_e - base);
    __shared__ float t1s[GA_G][R_DIM];
    __shared__ int sl[GA_G];
    int tid = threadIdx.x;
    if (tid < GA_G) sl[tid] = (tid < cnt) ? g_list[g_off[e] + base + tid] : -1;
    __syncthreads();
    if (tid < GA_G * R_DIM) {
        int s = tid >> 4, r = tid & 15;
        int ps = sl[s];
        t1s[s][r] = (ps >= 0) ? g_t1[ps * R_DIM + r] : 0.f;
    }
    __syncthreads();
    const float* B1e = B1mat + (size_t)e * H_DIM * R_DIM;
    for (int h = tid; h < H_DIM; h += 256) {
        const float4* br = (const float4*)(B1e + (size_t)h * R_DIM);
        float4 v0 = br[0], v1 = br[1], v2 = br[2], v3 = br[3];
        float bb = b1[h];
        #pragma unroll
        for (int s = 0; s < GA_G; s++) {
            int ps = sl[s];
            if (ps >= 0) {
                float lor = v0.x * t1s[s][0]  + v0.y * t1s[s][1]  + v0.z * t1s[s][2]  + v0.w * t1s[s][3]
                          + v1.x * t1s[s][4]  + v1.y * t1s[s][5]  + v1.z * t1s[s][6]  + v1.w * t1s[s][7]
                          + v2.x * t1s[s][8]  + v2.y * t1s[s][9]  + v2.z * t1s[s][10] + v2.w * t1s[s][11]
                          + v3.x * t1s[s][12] + v3.y * t1s[s][13] + v3.z * t1s[s][14] + v3.w * t1s[s][15];
                float val = __half2float(g_commonh[(size_t)(ps >> 1) * H_DIM + h]) + bb + LSCALE * lor;
                float a = __fdividef(val, 1.f + __expf(-val));
                g_acth[(size_t)ps * H_DIM + h] = __float2half_rn(a);
            }
        }
    }
}

// ---------------- combine ----------------
__global__ void combine_kernel(const float* __restrict__ B2mat, const float* __restrict__ b2,
                               float* __restrict__ out) {
    int t = blockIdx.x;
    __shared__ float t2s[2][R_DIM];
    __shared__ float wsh[2];
    __shared__ int esh[2];
    if (threadIdx.x < 2 * R_DIM) t2s[threadIdx.x >> 4][threadIdx.x & 15] = g_t2[t * 2 * R_DIM + threadIdx.x];
    if (threadIdx.x < 2) { wsh[threadIdx.x] = g_wt[t * 2 + threadIdx.x]; esh[threadIdx.x] = g_sel[t * 2 + threadIdx.x]; }
    __syncthreads();
    for (int d = threadIdx.x; d < D_DIM; d += blockDim.x) {
        float val = 0.f;
        #pragma unroll
        for (int k = 0; k < 2; k++) {
            const float4* br = (const float4*)(B2mat + ((size_t)esh[k] * D_DIM + d) * R_DIM);
            float lor = 0.f;
            #pragma unroll
            for (int q = 0; q < 4; q++) {
                float4 v = br[q];
                lor += v.x * t2s[k][q * 4 + 0] + v.y * t2s[k][q * 4 + 1]
                     + v.z * t2s[k][q * 4 + 2] + v.w * t2s[k][q * 4 + 3];
            }
            val += wsh[k] * (g_base2[((size_t)t * 2 + k) * D_DIM + d] + b2[d] + LSCALE * lor);
        }
        out[(size_t)t * D_DIM + d] = val;
    }
}

// ---------------- launch ----------------
extern "C" void kernel_launch(void* const* d_in, const int* in_sizes, int n_in,
                              void* d_out, int out_size) {
    const float* x    = (const float*)d_in[0];
    const float* gate = (const float*)d_in[1];
    const float* W1   = (const float*)d_in[2];
    const float* b1   = (const float*)d_in[3];
    const float* W2   = (const float*)d_in[4];
    const float* b2   = (const float*)d_in[5];
    const float* A1   = (const float*)d_in[6];
    const float* B1   = (const float*)d_in[7];
    const float* A2   = (const float*)d_in[8];
    const float* B2   = (const float*)d_in[9];
    float* out = (float*)d_out;

    float *p_base2, *p_t1, *p_t2;
    __half *p_xh, *p_w1h, *p_w2h, *p_acth, *p_commonh;
    cudaGetSymbolAddress((void**)&p_base2,   g_base2);
    cudaGetSymbolAddress((void**)&p_t1,      g_t1);
    cudaGetSymbolAddress((void**)&p_t2,      g_t2);
    cudaGetSymbolAddress((void**)&p_xh,      g_xh);
    cudaGetSymbolAddress((void**)&p_w1h,     g_w1h);
    cudaGetSymbolAddress((void**)&p_w2h,     g_w2h);
    cudaGetSymbolAddress((void**)&p_acth,    g_acth);
    cudaGetSymbolAddress((void**)&p_commonh, g_commonh);

    cudaFuncSetAttribute(gemm_f16_kernel<__half>,
                         cudaFuncAttributeMaxDynamicSharedMemorySize, GSMEM);
    cudaFuncSetAttribute(gemm_f16_kernel<float>,
                         cudaFuncAttributeMaxDynamicSharedMemorySize, GSMEM);

    // 0. fp16 copies of GEMM inputs (first also zeroes expert counts)
    cvt_f32_f16<<<(N_TOK * D_DIM) / 2048, 256>>>(x, p_xh, N_TOK * D_DIM);
    cvt_f32_f16<<<(H_DIM * D_DIM) / 2048, 256>>>(W1, p_w1h, H_DIM * D_DIM);
    cvt_f32_f16<<<(D_DIM * H_DIM) / 2048, 256>>>(W2, p_w2h, D_DIM * H_DIM);

    // 1. router (fused expert count)
    router_kernel<<<N_TOK, 256>>>(x, gate);

    // 2. dispatch
    dispatch_prefix<<<1, 32>>>();
    dispatch_scatter<<<NSLOT / 256, 256>>>();

    // 3. common_fc1 = X @ W1^T  -> fp16
    {
        dim3 grid(H_DIM / 128, N_TOK / 128);
        gemm_f16_kernel<__half><<<grid, 256, GSMEM>>>(p_xh, p_w1h, p_commonh, N_TOK, H_DIM, D_DIM);
    }

    // 4. t1 = x @ A1[e]^T (fp16 x rows)
    lora_in_grouped_h<<<dim3(NSLOT / GL_G, E_NUM), 256>>>(p_xh, A1, p_t1, D_DIM, 1);

    // 5. a = silu(common + b1 + scale * t1 @ B1[e]^T) -> fp16
    act_grouped<<<dim3(NSLOT / GA_G, E_NUM), 256>>>(B1, b1);

    // 6. base2 = a @ W2^T -> fp32
    {
        dim3 grid(D_DIM / 128, NSLOT / 128);
        gemm_f16_kernel<float><<<grid, 256, GSMEM>>>(p_acth, p_w2h, p_base2, NSLOT, D_DIM, H_DIM);
    }

    // 7. t2 = a @ A2[e]^T (fp16 act rows)
    lora_in_grouped_h<<<dim3(NSLOT / GL_G, E_NUM), 256>>>(p_acth, A2, p_t2, H_DIM, 0);

    // 8. out
    combine_kernel<<<N_TOK, 256>>>(B2, b2, out);
}

// round 11
// speedup vs baseline: 2.9700x; 1.1299x over previous
#include <cuda_runtime.h>
#include <cuda_fp16.h>
#include <math.h>
#include <stdint.h>

#define N_TOK 2048
#define D_DIM 1024
#define H_DIM 4096
#define E_NUM 8
#define R_DIM 16
#define LSCALE 2.0f
#define NSLOT (2*N_TOK)

// ---------------- scratch ----------------
__device__ __half g_commonh[N_TOK * H_DIM];
__device__ __half g_acth[NSLOT * H_DIM];
__device__ float  g_base2[NSLOT * D_DIM];
__device__ float  g_t1[NSLOT * R_DIM];
__device__ float  g_t2[NSLOT * R_DIM];
__device__ int    g_sel[NSLOT];
__device__ float  g_wt[NSLOT];
__device__ int g_cnt[E_NUM];
__device__ int g_off[E_NUM];
__device__ int g_pos[E_NUM];
__device__ int g_list[NSLOT];
__device__ __half g_xh[N_TOK * D_DIM];
__device__ __half g_w1h[H_DIM * D_DIM];
__device__ __half g_w2h[D_DIM * H_DIM];

// ---------------- f32 -> f16 conversion (block 0 also zeroes expert counts) ----------------
__global__ void cvt_f32_f16(const float* __restrict__ in, __half* __restrict__ out, int n) {
    if (blockIdx.x == 0 && threadIdx.x < E_NUM) g_cnt[threadIdx.x] = 0;
    int i = (blockIdx.x * 256 + threadIdx.x) * 8;
    if (i >= n) return;
    float4 v0 = *(const float4*)(in + i);
    float4 v1 = *(const float4*)(in + i + 4);
    __half2 h[4];
    h[0] = __floats2half2_rn(v0.x, v0.y);
    h[1] = __floats2half2_rn(v0.z, v0.w);
    h[2] = __floats2half2_rn(v1.x, v1.y);
    h[3] = __floats2half2_rn(v1.z, v1.w);
    *(uint4*)(out + i) = *(uint4*)h;
}

// ---------------- router (fused expert count) ----------------
__global__ void router_kernel(const float* __restrict__ x, const float* __restrict__ gate) {
    int t = blockIdx.x;
    int warp = threadIdx.x >> 5, lane = threadIdx.x & 31;
    __shared__ float logits[E_NUM];
    const float4* xr = (const float4*)(x + (size_t)t * D_DIM);
    const float4* gr = (const float4*)(gate + (size_t)warp * D_DIM);
    float s = 0.f;
    for (int i = lane; i < D_DIM / 4; i += 32) {
        float4 a = xr[i], b = gr[i];
        s += a.x * b.x + a.y * b.y + a.z * b.z + a.w * b.w;
    }
    #pragma unroll
    for (int o = 16; o; o >>= 1) s += __shfl_xor_sync(0xffffffffu, s, o);
    if (lane == 0) logits[warp] = s;
    __syncthreads();
    if (threadIdx.x == 0) {
        float best = -1e30f; int i0 = 0;
        #pragma unroll
        for (int e = 0; e < E_NUM; e++) if (logits[e] > best) { best = logits[e]; i0 = e; }
        float best2 = -1e30f; int i1 = 0;
        #pragma unroll
        for (int e = 0; e < E_NUM; e++) if (e != i0 && logits[e] > best2) { best2 = logits[e]; i1 = e; }
        float p1 = expf(best2 - best);
        float inv = 1.f / (1.f + p1);
        g_sel[t * 2 + 0] = i0; g_sel[t * 2 + 1] = i1;
        g_wt[t * 2 + 0] = inv; g_wt[t * 2 + 1] = p1 * inv;
        atomicAdd(&g_cnt[i0], 1);
        atomicAdd(&g_cnt[i1], 1);
    }
}

// ---------------- dispatch ----------------
__global__ void dispatch_prefix() {
    if (threadIdx.x == 0) {
        int o = 0;
        for (int e = 0; e < E_NUM; e++) { g_off[e] = o; g_pos[e] = o; o += g_cnt[e]; }
    }
}
__global__ void dispatch_scatter() {
    int i = blockIdx.x * 256 + threadIdx.x;
    if (i < NSLOT) {
        int e = g_sel[i];
        int pos = atomicAdd(&g_pos[e], 1);
        g_list[pos] = i;
    }
}

// ---------------- fp16 GEMM: 3-stage cp.async + ldmatrix fragments ----------------
// C[M,N] = A[M,K] @ B[N,K]^T, fp16 in, f32 accum, CT out (float or half).
// 128x128 tile, BK=32, 256 thr (8 warps 4x2), warp tile 32x64 via m16n8k16.
__device__ __forceinline__ void mma_f16(float* c, const unsigned* a, const unsigned* b) {
    asm volatile(
        "mma.sync.aligned.m16n8k16.row.col.f32.f16.f16.f32 "
        "{%0,%1,%2,%3}, {%4,%5,%6,%7}, {%8,%9}, {%0,%1,%2,%3};"
        : "+f"(c[0]), "+f"(c[1]), "+f"(c[2]), "+f"(c[3])
        : "r"(a[0]), "r"(a[1]), "r"(a[2]), "r"(a[3]), "r"(b[0]), "r"(b[1]));
}
__device__ __forceinline__ void ldsm_x4(unsigned* r, uint32_t addr) {
    asm volatile("ldmatrix.sync.aligned.m8n8.x4.shared.b16 {%0,%1,%2,%3}, [%4];"
        : "=r"(r[0]), "=r"(r[1]), "=r"(r[2]), "=r"(r[3]) : "r"(addr));
}
__device__ __forceinline__ uint32_t smem_u32(const void* p) {
    uint32_t a;
    asm("{ .reg .u64 t; cvta.to.shared.u64 t, %1; cvt.u32.u64 %0, t; }" : "=r"(a) : "l"(p));
    return a;
}
__device__ __forceinline__ void cp_async16(uint32_t dst, const void* src) {
    asm volatile("cp.async.ca.shared.global [%0], [%1], 16;" :: "r"(dst), "l"(src));
}
#define CP_COMMIT() asm volatile("cp.async.commit_group;" ::: "memory")
#define CP_WAIT(n)  asm volatile("cp.async.wait_group %0;" :: "n"(n) : "memory")

__device__ __forceinline__ void store2(float* p, float x, float y) { p[0] = x; p[1] = y; }
__device__ __forceinline__ void store2(__half* p, float x, float y) {
    *(__half2*)p = __floats2half2_rn(x, y);
}

#define GSTRH 40                      // halves per row (32 + 8 pad)
#define GHTILE (128 * GSTRH)          // halves per matrix per stage
#define GSTAGEB (2 * GHTILE * 2)      // bytes per stage (A+B)
#define GSMEM (3 * GSTAGEB)           // 61440 B

template <typename CT>
__global__ __launch_bounds__(256)
void gemm_f16_kernel(const __half* __restrict__ A, const __half* __restrict__ B,
                     CT* __restrict__ C, int M, int N, int K) {
    extern __shared__ __half smh[];
    uint32_t sb = smem_u32(smh);
    int bm = blockIdx.y * 128, bn = blockIdx.x * 128;
    int tid = threadIdx.x;
    int lane = tid & 31, wid = tid >> 5;
    int wm = (wid >> 1) * 32, wn = (wid & 1) * 64;
    int g = lane >> 2, tg = lane & 3;

    // copy slots: 512 16B chunks per matrix per tile; 2 per thread each
    int row0 = (tid * 2) >> 2,     q0 = (tid * 2) & 3;
    int row1 = (tid * 2 + 1) >> 2, q1 = (tid * 2 + 1) & 3;
    const char* Ap0 = (const char*)(A + (size_t)(bm + row0) * K + q0 * 8);
    const char* Ap1 = (const char*)(A + (size_t)(bm + row1) * K + q1 * 8);
    const char* Bp0 = (const char*)(B + (size_t)(bn + row0) * K + q0 * 8);
    const char* Bp1 = (const char*)(B + (size_t)(bn + row1) * K + q1 * 8);
    uint32_t oA0 = (uint32_t)(row0 * GSTRH + q0 * 8) * 2;
    uint32_t oA1 = (uint32_t)(row1 * GSTRH + q1 * 8) * 2;
    uint32_t oB0 = (uint32_t)GHTILE * 2 + oA0;
    uint32_t oB1 = (uint32_t)GHTILE * 2 + oA1;

    // ldmatrix per-thread address offsets (bytes, within stage)
    // A (mt): row = wm + mt*16 + (lane&15); col = (lane&16 ? 8 : 0)  [+ kg*16]
    uint32_t laA[2];
    #pragma unroll
    for (int mt = 0; mt < 2; mt++)
        laA[mt] = (uint32_t)((wm + mt * 16 + (lane & 15)) * GSTRH + ((lane & 16) ? 8 : 0)) * 2;
    // B (pair p): row = wn + 16p + (lane&7) + (lane&16 ? 8 : 0); col = (lane&8 ? 8 : 0)
    uint32_t laB[4];
    #pragma unroll
    for (int p = 0; p < 4; p++)
        laB[p] = (uint32_t)GHTILE * 2 +
                 (uint32_t)((wn + 16 * p + (lane & 7) + ((lane & 16) ? 8 : 0)) * GSTRH +
                            ((lane & 8) ? 8 : 0)) * 2;

    float acc[2][8][4];
    #pragma unroll
    for (int mt = 0; mt < 2; mt++)
        #pragma unroll
        for (int nt = 0; nt < 8; nt++)
            #pragma unroll
            for (int i = 0; i < 4; i++) acc[mt][nt][i] = 0.f;

    int ntk = K >> 5;

    // prologue: prefetch tiles 0, 1
    #pragma unroll
    for (int s = 0; s < 2; s++) {
        uint32_t st = sb + s * GSTAGEB;
        size_t ko = (size_t)s * 64;
        cp_async16(st + oA0, Ap0 + ko); cp_async16(st + oA1, Ap1 + ko);
        cp_async16(st + oB0, Bp0 + ko); cp_async16(st + oB1, Bp1 + ko);
        CP_COMMIT();
    }

    for (int kt = 0; kt < ntk; kt++) {
        int b = kt % 3;
        if (kt + 1 < ntk) { CP_WAIT(1); } else { CP_WAIT(0); }
        __syncthreads();
        if (kt + 2 < ntk) {
            int s = (kt + 2) % 3;
            uint32_t st = sb + s * GSTAGEB;
            size_t ko = (size_t)(kt + 2) * 64;
            cp_async16(st + oA0, Ap0 + ko); cp_async16(st + oA1, Ap1 + ko);
            cp_async16(st + oB0, Bp0 + ko); cp_async16(st + oB1, Bp1 + ko);
            CP_COMMIT();
        }
        uint32_t stg = sb + b * GSTAGEB;
        #pragma unroll
        for (int kg = 0; kg < 2; kg++) {
            uint32_t kofs = kg * 32;   // 16 halves
            unsigned av[2][4], bv[4][4];
            #pragma unroll
            for (int mt = 0; mt < 2; mt++)
                ldsm_x4(av[mt], stg + laA[mt] + kofs);
            #pragma unroll
            for (int p = 0; p < 4; p++)
                ldsm_x4(bv[p], stg + laB[p] + kofs);
            #pragma unroll
            for (int mt = 0; mt < 2; mt++)
                #pragma unroll
                for (int nt = 0; nt < 8; nt++)
                    mma_f16(acc[mt][nt], av[mt], &bv[nt >> 1][(nt & 1) * 2]);
        }
    }

    #pragma unroll
    for (int mt = 0; mt < 2; mt++) {
        #pragma unroll
        for (int nt = 0; nt < 8; nt++) {
            int r0 = bm + wm + mt * 16 + g;
            int c0 = bn + wn + nt * 8 + 2 * tg;
            store2(C + (size_t)r0 * N + c0,       acc[mt][nt][0], acc[mt][nt][1]);
            store2(C + (size_t)(r0 + 8) * N + c0, acc[mt][nt][2], acc[mt][nt][3]);
        }
    }
}

// ---------------- grouped rank-16 down-projection (fp16 input rows) ----------------
#define GL_G 32
#define GL_KC 128
__global__ __launch_bounds__(256)
void lora_in_grouped_h(const __half* __restrict__ X, const float* __restrict__ Amat,
                       float* __restrict__ Tout, int K, int tok_row) {
    int e = blockIdx.y;
    int n_e = g_cnt[e];
    int base = blockIdx.x * GL_G;
    if (base >= n_e) return;
    __shared__ float As[R_DIM][GL_KC];
    __shared__ int sl[GL_G];
    int tid = threadIdx.x, lane = tid & 31, w = tid >> 5;
    if (tid < GL_G) {
        int j = base + tid;
        sl[tid] = (j < n_e) ? g_list[g_off[e] + j] : -1;
    }
    __syncthreads();
    int p[4];
    const __half* xr[4];
    #pragma unroll
    for (int s = 0; s < 4; s++) {
        p[s] = sl[w * 4 + s];
        int row = (p[s] < 0) ? 0 : (tok_row ? (p[s] >> 1) : p[s]);
        xr[s] = X + (size_t)row * K;
    }
    float acc[4][R_DIM];
    #pragma unroll
    for (int s = 0; s < 4; s++)
        #pragma unroll
        for (int r = 0; r < R_DIM; r++) acc[s][r] = 0.f;

    const float* Ae = Amat + (size_t)e * R_DIM * K;
    for (int k0 = 0; k0 < K; k0 += GL_KC) {
        __syncthreads();
        #pragma unroll
        for (int l = 0; l < 2; l++) {
            int i = tid * 2 + l;
            int r = i >> 5, kq = i & 31;
            *(float4*)&As[r][kq * 4] = *(const float4*)(Ae + (size_t)r * K + k0 + kq * 4);
        }
        __syncthreads();
        float4 xv[4];
        #pragma unroll
        for (int s = 0; s < 4; s++) {
            __half2 h01 = *(const __half2*)(xr[s] + k0 + lane * 4);
            __half2 h23 = *(const __half2*)(xr[s] + k0 + lane * 4 + 2);
            float2 f01 = __half22float2(h01);
            float2 f23 = __half22float2(h23);
            xv[s] = make_float4(f01.x, f01.y, f23.x, f23.y);
        }
        #pragma unroll
        for (int r = 0; r < R_DIM; r++) {
            float4 a4 = *(const float4*)&As[r][lane * 4];
            #pragma unroll
            for (int s = 0; s < 4; s++)
                acc[s][r] += xv[s].x * a4.x + xv[s].y * a4.y + xv[s].z * a4.z + xv[s].w * a4.w;
        }
    }
    #pragma unroll
    for (int s = 0; s < 4; s++) {
        #pragma unroll
        for (int r = 0; r < R_DIM; r++) {
            float v = acc[s][r];
            v += __shfl_xor_sync(0xffffffffu, v, 16);
            v += __shfl_xor_sync(0xffffffffu, v, 8);
            v += __shfl_xor_sync(0xffffffffu, v, 4);
            v += __shfl_xor_sync(0xffffffffu, v, 2);
            v += __shfl_xor_sync(0xffffffffu, v, 1);
            if (lane == 0 && p[s] >= 0) Tout[p[s] * R_DIM + r] = v;
        }
    }
}

// ---------------- grouped fc1 epilogue (half in/out, fast silu) ----------------
#define GA_G 16
__global__ __launch_bounds__(256)
void act_grouped(const float* __restrict__ B1mat, const float* __restrict__ b1) {
    int e = blockIdx.y;
    int n_e = g_cnt[e];
    int base = blockIdx.x * GA_G;
    if (base >= n_e) return;
    int cnt = min(GA_G, n_e - base);
    __shared__ float t1s[GA_G][R_DIM];
    __shared__ int sl[GA_G];
    int tid = threadIdx.x;
    if (tid < GA_G) sl[tid] = (tid < cnt) ? g_list[g_off[e] + base + tid] : -1;
    __syncthreads();
    if (tid < GA_G * R_DIM) {
        int s = tid >> 4, r = tid & 15;
        int ps = sl[s];
        t1s[s][r] = (ps >= 0) ? g_t1[ps * R_DIM + r] : 0.f;
    }
    __syncthreads();
    const float* B1e = B1mat + (size_t)e * H_DIM * R_DIM;
    for (int h = tid; h < H_DIM; h += 256) {
        const float4* br = (const float4*)(B1e + (size_t)h * R_DIM);
        float4 v0 = br[0], v1 = br[1], v2 = br[2], v3 = br[3];
        float bb = b1[h];
        #pragma unroll
        for (int s = 0; s < GA_G; s++) {
            int ps = sl[s];
            if (ps >= 0) {
                float lor = v0.x * t1s[s][0]  + v0.y * t1s[s][1]  + v0.z * t1s[s][2]  + v0.w * t1s[s][3]
                          + v1.x * t1s[s][4]  + v1.y * t1s[s][5]  + v1.z * t1s[s][6]  + v1.w * t1s[s][7]
                          + v2.x * t1s[s][8]  + v2.y * t1s[s][9]  + v2.z * t1s[s][10] + v2.w * t1s[s][11]
                          + v3.x * t1s[s][12] + v3.y * t1s[s][13] + v3.z * t1s[s][14] + v3.w * t1s[s][15];
                float val = __half2float(g_commonh[(size_t)(ps >> 1) * H_DIM + h]) + bb + LSCALE * lor;
                float a = __fdividef(val, 1.f + __expf(-val));
                g_acth[(size_t)ps * H_DIM + h] = __float2half_rn(a);
            }
        }
    }
}

// ---------------- combine ----------------
__global__ void combine_kernel(const float* __restrict__ B2mat, const float* __restrict__ b2,
                               float* __restrict__ out) {
    int t = blockIdx.x;
    __shared__ float t2s[2][R_DIM];
    __shared__ float wsh[2];
    __shared__ int esh[2];
    if (threadIdx.x < 2 * R_DIM) t2s[threadIdx.x >> 4][threadIdx.x & 15] = g_t2[t * 2 * R_DIM + threadIdx.x];
    if (threadIdx.x < 2) { wsh[threadIdx.x] = g_wt[t * 2 + threadIdx.x]; esh[threadIdx.x] = g_sel[t * 2 + threadIdx.x]; }
    __syncthreads();
    for (int d = threadIdx.x; d < D_DIM; d += blockDim.x) {
        float val = 0.f;
        #pragma unroll
        for (int k = 0; k < 2; k++) {
            const float4* br = (const float4*)(B2mat + ((size_t)esh[k] * D_DIM + d) * R_DIM);
            float lor = 0.f;
            #pragma unroll
            for (int q = 0; q < 4; q++) {
                float4 v = br[q];
                lor += v.x * t2s[k][q * 4 + 0] + v.y * t2s[k][q * 4 + 1]
                     + v.z * t2s[k][q * 4 + 2] + v.w * t2s[k][q * 4 + 3];
            }
            val += wsh[k] * (g_base2[((size_t)t * 2 + k) * D_DIM + d] + b2[d] + LSCALE * lor);
        }
        out[(size_t)t * D_DIM + d] = val;
    }
}

// ---------------- launch ----------------
extern "C" void kernel_launch(void* const* d_in, const int* in_sizes, int n_in,
                              void* d_out, int out_size) {
    const float* x    = (const float*)d_in[0];
    const float* gate = (const float*)d_in[1];
    const float* W1   = (const float*)d_in[2];
    const float* b1   = (const float*)d_in[3];
    const float* W2   = (const float*)d_in[4];
    const float* b2   = (const float*)d_in[5];
    const float* A1   = (const float*)d_in[6];
    const float* B1   = (const float*)d_in[7];
    const float* A2   = (const float*)d_in[8];
    const float* B2   = (const float*)d_in[9];
    float* out = (float*)d_out;

    float *p_base2, *p_t1, *p_t2;
    __half *p_xh, *p_w1h, *p_w2h, *p_acth, *p_commonh;
    cudaGetSymbolAddress((void**)&p_base2,   g_base2);
    cudaGetSymbolAddress((void**)&p_t1,      g_t1);
    cudaGetSymbolAddress((void**)&p_t2,      g_t2);
    cudaGetSymbolAddress((void**)&p_xh,      g_xh);
    cudaGetSymbolAddress((void**)&p_w1h,     g_w1h);
    cudaGetSymbolAddress((void**)&p_w2h,     g_w2h);
    cudaGetSymbolAddress((void**)&p_acth,    g_acth);
    cudaGetSymbolAddress((void**)&p_commonh, g_commonh);

    cudaFuncSetAttribute(gemm_f16_kernel<__half>,
                         cudaFuncAttributeMaxDynamicSharedMemorySize, GSMEM);
    cudaFuncSetAttribute(gemm_f16_kernel<float>,
                         cudaFuncAttributeMaxDynamicSharedMemorySize, GSMEM);

    // 0. fp16 copies of GEMM inputs (first also zeroes expert counts)
    cvt_f32_f16<<<(N_TOK * D_DIM) / 2048, 256>>>(x, p_xh, N_TOK * D_DIM);
    cvt_f32_f16<<<(H_DIM * D_DIM) / 2048, 256>>>(W1, p_w1h, H_DIM * D_DIM);
    cvt_f32_f16<<<(D_DIM * H_DIM) / 2048, 256>>>(W2, p_w2h, D_DIM * H_DIM);

    // 1. router (fused expert count)
    router_kernel<<<N_TOK, 256>>>(x, gate);

    // 2. dispatch
    dispatch_prefix<<<1, 32>>>();
    dispatch_scatter<<<NSLOT / 256, 256>>>();

    // 3. common_fc1 = X @ W1^T  -> fp16
    {
        dim3 grid(H_DIM / 128, N_TOK / 128);
        gemm_f16_kernel<__half><<<grid, 256, GSMEM>>>(p_xh, p_w1h, p_commonh, N_TOK, H_DIM, D_DIM);
    }

    // 4. t1 = x @ A1[e]^T (fp16 x rows)
    lora_in_grouped_h<<<dim3(NSLOT / GL_G, E_NUM), 256>>>(p_xh, A1, p_t1, D_DIM, 1);

    // 5. a = silu(common + b1 + scale * t1 @ B1[e]^T) -> fp16
    act_grouped<<<dim3(NSLOT / GA_G, E_NUM), 256>>>(B1, b1);

    // 6. base2 = a @ W2^T -> fp32
    {
        dim3 grid(D_DIM / 128, NSLOT / 128);
        gemm_f16_kernel<float><<<grid, 256, GSMEM>>>(p_acth, p_w2h, p_base2, NSLOT, D_DIM, H_DIM);
    }

    // 7. t2 = a @ A2[e]^T (fp16 act rows)
    lora_in_grouped_h<<<dim3(NSLOT / GL_G, E_NUM), 256>>>(p_acth, A2, p_t2, H_DIM, 0);

    // 8. out
    combine_kernel<<<N_TOK, 256>>>(B2, b2, out);
}